// round 6
// baseline (speedup 1.0000x reference)
#include <cuda_runtime.h>
#include <cuda_bf16.h>
#include <mma.h>
#include <cstdint>

using namespace nvcuda;

#define N_NODES 1024
#define N_EDGES 32768
#define KE 32
#define KOUT 32
#define DIN 64
#define DOUT 64
#define DNODE 64
#define KW 160
#define HID 256
#define N_TILES (N_EDGES / 128)   // 256

// -------- device scratch (static; no runtime allocation) --------
__device__ float g_h[N_NODES * DNODE];
__device__ float g_X4[N_EDGES * KE];
__device__ float g_X5[N_EDGES * KE];
__device__ float g_prod[N_EDGES * KE];    // (SP W2^T)*(SP W3^T)
__device__ float g_path[N_EDGES * KE];    // tmp_matmul
__device__ int   g_eid[N_NODES * N_NODES];
__device__ int   g_rowcnt[N_NODES];
__device__ int   g_fill[N_NODES];
__device__ int   g_rowptr[N_NODES + 1];
__device__ int   g_rowedges[N_EDGES];
__device__ float g_AGG[N_NODES * KOUT * DIN];

// bf16 two-term weights (row-major)
__device__ __align__(16) __nv_bfloat16 g_W6h[HID * KW];
__device__ __align__(16) __nv_bfloat16 g_W6l[HID * KW];
__device__ __align__(16) __nv_bfloat16 g_W7h[KOUT * HID];
__device__ __align__(16) __nv_bfloat16 g_W7l[KOUT * HID];

__device__ __forceinline__ void bf16_split(float v, __nv_bfloat16& h, __nv_bfloat16& l) {
    h = __float2bfloat16(v);
    l = __float2bfloat16(v - __bfloat162float(h));
}

// split float4 -> 4 bf16 hi + 4 bf16 lo, packed bf16x2 smem stores (idx 4-aligned)
__device__ __forceinline__ void pack4(__nv_bfloat16* H, __nv_bfloat16* L, int idx, float4 v) {
    __nv_bfloat16 h0, h1, h2, h3, l0, l1, l2, l3;
    bf16_split(v.x, h0, l0); bf16_split(v.y, h1, l1);
    bf16_split(v.z, h2, l2); bf16_split(v.w, h3, l3);
    __nv_bfloat162* ph = (__nv_bfloat162*)&H[idx];
    __nv_bfloat162* pl = (__nv_bfloat162*)&L[idx];
    __nv_bfloat162 a; a.x = h0; a.y = h1; ph[0] = a;
    __nv_bfloat162 b; b.x = h2; b.y = h3; ph[1] = b;
    __nv_bfloat162 c; c.x = l0; c.y = l1; pl[0] = c;
    __nv_bfloat162 d; d.x = l2; d.y = l3; pl[1] = d;
}

// ---------------------------------------------------------------
__global__ void k_init() {
    int idx = blockIdx.x * blockDim.x + threadIdx.x;
    int stride = gridDim.x * blockDim.x;
    for (int i = idx; i < N_NODES * N_NODES; i += stride) g_eid[i] = -1;
    if (idx < N_NODES) { g_rowcnt[idx] = 0; g_fill[idx] = 0; }
}

__global__ void k_h(const float* __restrict__ x, const float* __restrict__ Wnode) {
    __shared__ float xs[DIN];
    __shared__ float ws[DNODE][DIN + 1];
    int n = blockIdx.x;
    int t = threadIdx.x;  // 64
    xs[t] = x[n * DIN + t];
    for (int r = 0; r < DNODE; r++) ws[r][t] = Wnode[r * DIN + t];
    __syncthreads();
    float acc = 0.f;
#pragma unroll
    for (int c = 0; c < DIN; c++) acc += xs[c] * ws[t][c];
    g_h[n * DNODE + t] = acc;
}

// convert W6 / W7 to bf16 hi/lo
__global__ void k_wconv(const float* __restrict__ W6, const float* __restrict__ W7) {
    int i = blockIdx.x * blockDim.x + threadIdx.x;
    if (i < HID * KW) {
        __nv_bfloat16 h, l;
        bf16_split(W6[i], h, l);
        g_W6h[i] = h; g_W6l[i] = l;
    } else if (i < HID * KW + KOUT * HID) {
        int j = i - HID * KW;
        __nv_bfloat16 h, l;
        bf16_split(W7[j], h, l);
        g_W7h[j] = h; g_W7l[j] = l;
    }
}

// per-edge small GEMMs via register weights + shfl broadcast (zero inner-loop LDS).
// warp type 0: W2/W3 -> g_prod;  type 1: W4/W5 -> g_X4, g_X5.
__global__ __launch_bounds__(256) void k_edgex(const float* __restrict__ SP,
                                               const float* __restrict__ W2,
                                               const float* __restrict__ W3,
                                               const float* __restrict__ W4,
                                               const float* __restrict__ W5) {
    __shared__ float sw[4][KE * KE];
    int t = threadIdx.x;
    for (int i = t; i < KE * KE; i += 256) {
        sw[0][i] = W2[i]; sw[1][i] = W3[i]; sw[2][i] = W4[i]; sw[3][i] = W5[i];
    }
    __syncthreads();
    int w = t >> 5, lane = t & 31;
    int type = w & 1;
    int pair = blockIdx.x * 4 + (w >> 1);   // 4096 pairs, 8 edges each
    float wa[32], wb[32];
    const float* A = sw[type * 2];
    const float* B = sw[type * 2 + 1];
#pragma unroll
    for (int j = 0; j < 32; j++) { wa[j] = A[lane * 32 + j]; wb[j] = B[lane * 32 + j]; }
#pragma unroll
    for (int it = 0; it < 8; it++) {
        int e = pair * 8 + it;
        float spv = SP[(size_t)e * KE + lane];
        float pa = 0.f, pb = 0.f;
#pragma unroll
        for (int j = 0; j < 32; j++) {
            float s = __shfl_sync(0xFFFFFFFFu, spv, j);
            pa += s * wa[j];
            pb += s * wb[j];
        }
        if (type == 0) {
            g_prod[(size_t)e * KE + lane] = pa * pb;
        } else {
            g_X4[(size_t)e * KE + lane] = pa;
            g_X5[(size_t)e * KE + lane] = pb;
        }
    }
}

__global__ void k_build(const int* __restrict__ ei) {
    int e = blockIdx.x * blockDim.x + threadIdx.x;
    if (e < N_EDGES) {
        int s = ei[e], d = ei[N_EDGES + e];
        g_eid[s * N_NODES + d] = e;
        atomicAdd(&g_rowcnt[s], 1);
    }
}

__global__ void k_scan() {
    __shared__ int s[N_NODES];
    int t = threadIdx.x;
    s[t] = g_rowcnt[t];
    __syncthreads();
    for (int off = 1; off < N_NODES; off <<= 1) {
        int v = (t >= off) ? s[t - off] : 0;
        __syncthreads();
        s[t] += v;
        __syncthreads();
    }
    g_rowptr[t + 1] = s[t];
    if (t == 0) g_rowptr[0] = 0;
}

__global__ void k_fill(const int* __restrict__ ei) {
    int e = blockIdx.x * blockDim.x + threadIdx.x;
    if (e < N_EDGES) {
        int s = ei[e];
        int pos = atomicAdd(&g_fill[s], 1);
        g_rowedges[g_rowptr[s] + pos] = e;
    }
}

// sampled sparse-sparse matmul -> g_path
__global__ void k_path(const int* __restrict__ ei) {
    int warp = (blockIdx.x * blockDim.x + threadIdx.x) >> 5;
    int lane = threadIdx.x & 31;
    if (warp >= N_EDGES) return;
    int e = warp;
    int i = ei[e], j = ei[N_EDGES + e];
    int start = g_rowptr[i], end = g_rowptr[i + 1];
    float acc = 0.f;
    for (int s = start; s < end; s += 32) {
        int idx = s + lane;
        int e1 = -1, e2 = -1;
        if (idx < end) {
            e1 = g_rowedges[idx];
            int m = ei[N_EDGES + e1];
            e2 = g_eid[m * N_NODES + j];
        }
        unsigned mask = __ballot_sync(0xFFFFFFFFu, e2 >= 0);
        while (mask) {
            int b = __ffs(mask) - 1;
            mask &= mask - 1;
            int E1 = __shfl_sync(0xFFFFFFFFu, e1, b);
            int E2 = __shfl_sync(0xFFFFFFFFu, e2, b);
            acc += g_X4[E1 * KE + lane] * g_X5[E2 * KE + lane];
        }
    }
    g_path[(size_t)e * KE + lane] = acc;
}

// ---------------- fused WMMA edge MLP: EA = relu(TMP@W6^T)@W7^T ----------------
#define AS_LD   168
#define W6S_LD  168
#define W7S_LD  264
#define HS_LD   72
#define OFF_AH  0
#define OFF_AL  (OFF_AH + 128 * AS_LD * 2)        // 43008
#define OFF_W6H (OFF_AL + 128 * AS_LD * 2)        // 86016
#define OFF_W6L (OFF_W6H + 64 * W6S_LD * 2)       // 107520
#define OFF_W7H (OFF_W6L + 64 * W6S_LD * 2)       // 129024
#define OFF_W7L (OFF_W7H + 32 * W7S_LD * 2)       // 145920
#define OFF_HH  (OFF_W7L + 32 * W7S_LD * 2)       // 162816
#define OFF_HL  (OFF_HH + 128 * HS_LD * 2)        // 181248
#define SMEM_FUSED (OFF_HL + 128 * HS_LD * 2)     // 199680
#define OFF_CBUF OFF_W6H                          // fp32 128x68 reuses W6 region
#define CB_LD   68
#define EB_LD   36

__global__ __launch_bounds__(256, 1) void k_fused(const float* __restrict__ SP,
                                                  const int* __restrict__ ei,
                                                  float* __restrict__ EA) {
    extern __shared__ char S[];
    int t = threadIdx.x;
    int w = t >> 5, lane = t & 31;
    int tile = blockIdx.x;

    __nv_bfloat16* sAh  = (__nv_bfloat16*)(S + OFF_AH);
    __nv_bfloat16* sAl  = (__nv_bfloat16*)(S + OFF_AL);
    __nv_bfloat16* sW6h = (__nv_bfloat16*)(S + OFF_W6H);
    __nv_bfloat16* sW6l = (__nv_bfloat16*)(S + OFF_W6L);
    __nv_bfloat16* sW7h = (__nv_bfloat16*)(S + OFF_W7H);
    __nv_bfloat16* sW7l = (__nv_bfloat16*)(S + OFF_W7L);
    __nv_bfloat16* sHh  = (__nv_bfloat16*)(S + OFF_HH);
    __nv_bfloat16* sHl  = (__nv_bfloat16*)(S + OFF_HL);
    float* Cbuf = (float*)(S + OFF_CBUF);

    // ---- assemble A tile in bf16 hi/lo: [SP | prod | diag | path] ----
    {
        // cols [0:32) from SP, [32:64) from g_prod, [128:160) from g_path
        for (int i = t; i < 1024; i += 256) {           // 128 rows x 8 float4
            int r = i >> 3, c4 = (i & 7) << 2;
            size_t g = (size_t)(tile * 128 + r) * KE + c4;
            pack4(sAh, sAl, r * AS_LD + c4, *(const float4*)&SP[g]);
            pack4(sAh, sAl, r * AS_LD + 32 + c4, *(const float4*)&g_prod[g]);
            pack4(sAh, sAl, r * AS_LD + 128 + c4, *(const float4*)&g_path[g]);
        }
        // zero diag cols [64:128)  (64 bf16 = 32 uint per row, 4B-aligned: 168r+64 even)
        for (int i = t; i < 128 * 32; i += 256) {
            int r = i >> 5, u = i & 31;
            ((uint32_t*)&sAh[r * AS_LD + 64])[u] = 0u;
            ((uint32_t*)&sAl[r * AS_LD + 64])[u] = 0u;
        }
        // full W7 (hi/lo)
        const uint4* wH = (const uint4*)g_W7h;
        const uint4* wL = (const uint4*)g_W7l;
        for (int i = t; i < 32 * 32; i += 256) {        // 32 uint4 per 256-el row
            int r = i / 32, sgi = i % 32;
            *(uint4*)&sW7h[r * W7S_LD + sgi * 8] = wH[i];
            *(uint4*)&sW7l[r * W7S_LD + sgi * 8] = wL[i];
        }
    }
    __syncthreads();
    // diag rows: overwrite zeros with h[src] where src==dst (rare)
    if (t < 128) {
        int e = tile * 128 + t;
        int si = ei[e], dj = ei[N_EDGES + e];
        if (si == dj) {
            for (int c = 0; c < 64; c++) {
                __nv_bfloat16 h, l;
                bf16_split(g_h[si * DNODE + c], h, l);
                sAh[t * AS_LD + 64 + c] = h;
                sAl[t * AS_LD + 64 + c] = l;
            }
        }
    }

    wmma::fragment<wmma::accumulator, 16, 16, 16, float> ea[2];
    wmma::fill_fragment(ea[0], 0.f);
    wmma::fill_fragment(ea[1], 0.f);

    for (int nc = 0; nc < 4; nc++) {
        __syncthreads();   // A/W7/diag ready (nc=0); Cbuf consumed (nc>0)
        // load W6 chunk rows [nc*64, nc*64+64)
        {
            const uint4* bH = (const uint4*)(g_W6h + (size_t)nc * 64 * KW);
            const uint4* bL = (const uint4*)(g_W6l + (size_t)nc * 64 * KW);
            for (int i = t; i < 64 * 20; i += 256) {
                int r = i / 20, sgi = i % 20;
                *(uint4*)&sW6h[r * W6S_LD + sgi * 8] = bH[i];
                *(uint4*)&sW6l[r * W6S_LD + sgi * 8] = bL[i];
            }
        }
        __syncthreads();

        // GEMM1 chunk: C[128,64] = A[128,160] @ W6c^T, warp w -> rows [w*16, w*16+16)
        wmma::fragment<wmma::accumulator, 16, 16, 16, float> c[4];
#pragma unroll
        for (int n = 0; n < 4; n++) wmma::fill_fragment(c[n], 0.f);
#pragma unroll
        for (int k = 0; k < 10; k++) {
            wmma::fragment<wmma::matrix_a, 16, 16, 16, __nv_bfloat16, wmma::row_major> ah, al;
            wmma::load_matrix_sync(ah, sAh + w * 16 * AS_LD + k * 16, AS_LD);
            wmma::load_matrix_sync(al, sAl + w * 16 * AS_LD + k * 16, AS_LD);
#pragma unroll
            for (int n = 0; n < 4; n++) {
                wmma::fragment<wmma::matrix_b, 16, 16, 16, __nv_bfloat16, wmma::col_major> bh, bl;
                wmma::load_matrix_sync(bh, sW6h + n * 16 * W6S_LD + k * 16, W6S_LD);
                wmma::load_matrix_sync(bl, sW6l + n * 16 * W6S_LD + k * 16, W6S_LD);
                wmma::mma_sync(c[n], ah, bh, c[n]);
                wmma::mma_sync(c[n], ah, bl, c[n]);
                wmma::mma_sync(c[n], al, bh, c[n]);
            }
        }
        __syncthreads();   // all warps done reading W6 chunk; Cbuf region free

        // store fp32 C, relu + split to bf16 hi/lo H chunk (warp-local rows)
#pragma unroll
        for (int n = 0; n < 4; n++)
            wmma::store_matrix_sync(Cbuf + w * 16 * CB_LD + n * 16, c[n], CB_LD, wmma::mem_row_major);
        __syncwarp();
#pragma unroll
        for (int idx = 0; idx < 32; idx++) {
            int f = lane + idx * 32;           // 0..1023
            int r = f >> 6, cc = f & 63;
            float v = fmaxf(Cbuf[(w * 16 + r) * CB_LD + cc], 0.f);
            __nv_bfloat16 h, l;
            bf16_split(v, h, l);
            sHh[(w * 16 + r) * HS_LD + cc] = h;
            sHl[(w * 16 + r) * HS_LD + cc] = l;
        }
        __syncwarp();

        // GEMM2 partial: EA[w rows] += Hc[16,64] @ W7c^T  (K cols nc*64..nc*64+64)
#pragma unroll
        for (int k2 = 0; k2 < 4; k2++) {
            wmma::fragment<wmma::matrix_a, 16, 16, 16, __nv_bfloat16, wmma::row_major> ah, al;
            wmma::load_matrix_sync(ah, sHh + w * 16 * HS_LD + k2 * 16, HS_LD);
            wmma::load_matrix_sync(al, sHl + w * 16 * HS_LD + k2 * 16, HS_LD);
#pragma unroll
            for (int n = 0; n < 2; n++) {
                wmma::fragment<wmma::matrix_b, 16, 16, 16, __nv_bfloat16, wmma::col_major> bh, bl;
                wmma::load_matrix_sync(bh, sW7h + n * 16 * W7S_LD + nc * 64 + k2 * 16, W7S_LD);
                wmma::load_matrix_sync(bl, sW7l + n * 16 * W7S_LD + nc * 64 + k2 * 16, W7S_LD);
                wmma::mma_sync(ea[n], ah, bh, ea[n]);
                wmma::mma_sync(ea[n], ah, bl, ea[n]);
                wmma::mma_sync(ea[n], al, bh, ea[n]);
            }
        }
    }

    // epilogue: EA frags -> smem -> coalesced global store
    __syncthreads();
    float* Ebuf = Cbuf;                        // 128 x 36 fp32
    wmma::store_matrix_sync(Ebuf + w * 16 * EB_LD, ea[0], EB_LD, wmma::mem_row_major);
    wmma::store_matrix_sync(Ebuf + w * 16 * EB_LD + 16, ea[1], EB_LD, wmma::mem_row_major);
    __syncthreads();
    for (int f = t; f < 1024; f += 256) {      // 128 rows x 8 float4
        int r = f >> 3, sgi = f & 7;
        float4 v = *(float4*)&Ebuf[r * EB_LD + sgi * 4];
        *(float4*)&EA[((size_t)tile * 128 + r) * KOUT + sgi * 4] = v;
    }
}

// ---------------- aggregation (batched) + output ----------------
__global__ void k_agg(const float* __restrict__ x, const int* __restrict__ ei,
                      const float* __restrict__ EA) {
    int i = blockIdx.x;
    int t = threadIdx.x;  // 256
    __shared__ float ea_b[8][33];
    __shared__ float x_b[8][64];
    __shared__ int elist[8], dlist[8];
    float acc[8];
#pragma unroll
    for (int q = 0; q < 8; q++) acc[q] = 0.f;
    int start = g_rowptr[i], end = g_rowptr[i + 1];
    int c = t & 63, k0 = t >> 6;
    for (int p = start; p < end; p += 8) {
        int nb = min(8, end - p);
        if (t < nb) {
            int e = g_rowedges[p + t];
            elist[t] = e;
            dlist[t] = ei[N_EDGES + e];
        }
        __syncthreads();
        for (int i2 = t; i2 < nb * 96; i2 += 256) {
            int b = i2 / 96, f = i2 % 96;
            if (f < 32) ea_b[b][f] = EA[(size_t)elist[b] * KOUT + f];
            else x_b[b][f - 32] = x[dlist[b] * DIN + f - 32];
        }
        __syncthreads();
        for (int b = 0; b < nb; b++) {
            float xv = x_b[b][c];
#pragma unroll
            for (int q = 0; q < 8; q++) acc[q] += ea_b[b][k0 + q * 4] * xv;
        }
        __syncthreads();
    }
#pragma unroll
    for (int q = 0; q < 8; q++) g_AGG[i * (KOUT * DIN) + t + q * 256] = acc[q];
}

__global__ void k_out(const float* __restrict__ CW, const float* __restrict__ CB,
                      float* __restrict__ xout) {
    __shared__ float As[32][32];
    __shared__ float Bs[32][68];
    int t = threadIdx.x;            // 256
    int tx = t & 15, ty = t >> 4;
    int rowBase = blockIdx.x * 32;
    const int KTOT = KOUT * DIN;    // 2048
    float acc[2][4] = {};
    for (int k0 = 0; k0 < KTOT; k0 += 32) {
        {
            int r = t >> 3, kk = (t & 7) << 2;
            float4 v = *(const float4*)&g_AGG[(rowBase + r) * KTOT + k0 + kk];
            *(float4*)&As[r][kk] = v;
        }
#pragma unroll
        for (int l = 0; l < 2; l++) {
            int fid = t + l * 256;
            int kk = fid >> 4, n4 = (fid & 15) << 2;
            float4 v = *(const float4*)&CW[(k0 + kk) * DOUT + n4];
            *(float4*)&Bs[kk][n4] = v;
        }
        __syncthreads();
#pragma unroll
        for (int kk = 0; kk < 32; kk++) {
            float a[2], b[4];
            a[0] = As[ty * 2][kk]; a[1] = As[ty * 2 + 1][kk];
            float4 bv = *(const float4*)&Bs[kk][tx * 4];
            b[0] = bv.x; b[1] = bv.y; b[2] = bv.z; b[3] = bv.w;
#pragma unroll
            for (int i = 0; i < 2; i++)
#pragma unroll
                for (int j = 0; j < 4; j++) acc[i][j] += a[i] * b[j];
        }
        __syncthreads();
    }
#pragma unroll
    for (int i = 0; i < 2; i++) {
        int r = rowBase + ty * 2 + i;
#pragma unroll
        for (int j = 0; j < 4; j++)
            xout[r * DOUT + tx * 4 + j] = acc[i][j] + CB[tx * 4 + j];
    }
}

// ---------------------------------------------------------------
extern "C" void kernel_launch(void* const* d_in, const int* in_sizes, int n_in,
                              void* d_out, int out_size) {
    const float* x     = (const float*)d_in[0];
    const int*   ei    = (const int*)  d_in[1];
    const float* SP    = (const float*)d_in[2];
    const float* Wnode = (const float*)d_in[4];
    const float* W2    = (const float*)d_in[5];
    const float* W3    = (const float*)d_in[6];
    const float* W4    = (const float*)d_in[7];
    const float* W5    = (const float*)d_in[8];
    const float* W6    = (const float*)d_in[9];
    const float* W7    = (const float*)d_in[10];
    const float* CW    = (const float*)d_in[11];
    const float* CB    = (const float*)d_in[12];

    float* xout = (float*)d_out;                       // [1024, 64]
    float* EA   = (float*)d_out + N_NODES * DOUT;      // [32768, 32]

    cudaFuncSetAttribute(k_fused, cudaFuncAttributeMaxDynamicSharedMemorySize, SMEM_FUSED);

    k_init<<<2048, 512>>>();
    k_h<<<N_NODES, 64>>>(x, Wnode);
    k_wconv<<<(HID * KW + KOUT * HID + 255) / 256, 256>>>(W6, W7);
    k_edgex<<<1024, 256>>>(SP, W2, W3, W4, W5);
    k_build<<<N_EDGES / 256, 256>>>(ei);
    k_scan<<<1, 1024>>>();
    k_fill<<<N_EDGES / 256, 256>>>(ei);
    k_path<<<N_EDGES / 8, 256>>>(ei);
    k_fused<<<N_TILES, 256, SMEM_FUSED>>>(SP, ei, EA);
    k_agg<<<N_NODES, 256>>>(x, ei, EA);
    k_out<<<N_NODES / 32, 256>>>(CW, CB, xout);
}

// round 7
// speedup vs baseline: 1.1299x; 1.1299x over previous
#include <cuda_runtime.h>
#include <cuda_bf16.h>
#include <mma.h>
#include <cstdint>

using namespace nvcuda;

#define N_NODES 1024
#define N_EDGES 32768
#define KE 32
#define KOUT 32
#define DIN 64
#define DOUT 64
#define DNODE 64
#define KW 160
#define HID 256
#define N_TILES (N_EDGES / 128)   // 256

// -------- device scratch (static; no runtime allocation) --------
__device__ float g_h[N_NODES * DNODE];
__device__ float g_X4[N_EDGES * KE];
__device__ float g_X5[N_EDGES * KE];
__device__ float g_prod[N_EDGES * KE];    // (SP W2^T)*(SP W3^T)
__device__ float g_path[N_EDGES * KE];    // tmp_matmul
__device__ int   g_eid[N_NODES * N_NODES];
__device__ int   g_rowcnt[N_NODES];
__device__ int   g_fill[N_NODES];
__device__ int   g_rowptr[N_NODES + 1];
__device__ int   g_rowedges[N_EDGES];
__device__ float g_AGG[N_NODES * KOUT * DIN];

// bf16 two-term weights (row-major)
__device__ __align__(16) __nv_bfloat16 g_W6h[HID * KW];
__device__ __align__(16) __nv_bfloat16 g_W6l[HID * KW];
__device__ __align__(16) __nv_bfloat16 g_W7h[KOUT * HID];
__device__ __align__(16) __nv_bfloat16 g_W7l[KOUT * HID];
// concat(W2,W3,W4,W5) as [128 n][32 k] bf16 hi/lo (col-major-fragment friendly)
__device__ __align__(16) __nv_bfloat16 g_W25h[128 * KE];
__device__ __align__(16) __nv_bfloat16 g_W25l[128 * KE];

__device__ __forceinline__ void bf16_split(float v, __nv_bfloat16& h, __nv_bfloat16& l) {
    h = __float2bfloat16(v);
    l = __float2bfloat16(v - __bfloat162float(h));
}

// split float4 -> 4 bf16 hi + 4 bf16 lo, packed bf16x2 smem stores (idx 4-aligned)
__device__ __forceinline__ void pack4(__nv_bfloat16* H, __nv_bfloat16* L, int idx, float4 v) {
    __nv_bfloat16 h0, h1, h2, h3, l0, l1, l2, l3;
    bf16_split(v.x, h0, l0); bf16_split(v.y, h1, l1);
    bf16_split(v.z, h2, l2); bf16_split(v.w, h3, l3);
    __nv_bfloat162* ph = (__nv_bfloat162*)&H[idx];
    __nv_bfloat162* pl = (__nv_bfloat162*)&L[idx];
    __nv_bfloat162 a; a.x = h0; a.y = h1; ph[0] = a;
    __nv_bfloat162 b; b.x = h2; b.y = h3; ph[1] = b;
    __nv_bfloat162 c; c.x = l0; c.y = l1; pl[0] = c;
    __nv_bfloat162 d; d.x = l2; d.y = l3; pl[1] = d;
}

// ---------------------------------------------------------------
__global__ void k_init() {
    int idx = blockIdx.x * blockDim.x + threadIdx.x;
    int stride = gridDim.x * blockDim.x;
    for (int i = idx; i < N_NODES * N_NODES; i += stride) g_eid[i] = -1;
    if (idx < N_NODES) { g_rowcnt[idx] = 0; g_fill[idx] = 0; }
}

__global__ void k_h(const float* __restrict__ x, const float* __restrict__ Wnode) {
    __shared__ float xs[DIN];
    __shared__ float ws[DNODE][DIN + 1];
    int n = blockIdx.x;
    int t = threadIdx.x;  // 64
    xs[t] = x[n * DIN + t];
    for (int r = 0; r < DNODE; r++) ws[r][t] = Wnode[r * DIN + t];
    __syncthreads();
    float acc = 0.f;
#pragma unroll
    for (int c = 0; c < DIN; c++) acc += xs[c] * ws[t][c];
    g_h[n * DNODE + t] = acc;
}

// convert W6 / W7 / concat(W2..W5) to bf16 hi/lo
__global__ void k_wconv(const float* __restrict__ W6, const float* __restrict__ W7,
                        const float* __restrict__ W2, const float* __restrict__ W3,
                        const float* __restrict__ W4, const float* __restrict__ W5) {
    int i = blockIdx.x * blockDim.x + threadIdx.x;
    if (i < HID * KW) {
        __nv_bfloat16 h, l;
        bf16_split(W6[i], h, l);
        g_W6h[i] = h; g_W6l[i] = l;
    } else if (i < HID * KW + KOUT * HID) {
        int j = i - HID * KW;
        __nv_bfloat16 h, l;
        bf16_split(W7[j], h, l);
        g_W7h[j] = h; g_W7l[j] = l;
    } else if (i < HID * KW + KOUT * HID + 128 * KE) {
        int j = i - (HID * KW + KOUT * HID);   // [0, 4096)
        int m = j >> 10;                        // which W
        int r = j & 1023;                       // n*32+k within that W
        const float* Ws = (m == 0) ? W2 : (m == 1) ? W3 : (m == 2) ? W4 : W5;
        __nv_bfloat16 h, l;
        bf16_split(Ws[r], h, l);
        g_W25h[j] = h; g_W25l[j] = l;
    }
}

// ---- WMMA batched small GEMM: [X2p|X3p|X4|X5] = SP @ [W2|W3|W4|W5]^T ----
#define EX_SP_LD 40
#define EX_W_LD  40
#define EX_P_LD  36
#define EXOFF_SPH 0
#define EXOFF_SPL (EXOFF_SPH + 128 * EX_SP_LD * 2)    // 10240
#define EXOFF_WH  (EXOFF_SPL + 128 * EX_SP_LD * 2)    // 20480
#define EXOFF_WL  (EXOFF_WH + 128 * EX_W_LD * 2)      // 30720
#define EXOFF_P2  (EXOFF_WL + 128 * EX_W_LD * 2)      // 40960
#define EXOFF_P3  (EXOFF_P2 + 128 * EX_P_LD * 4)      // 59392
#define SMEM_EDGEX (EXOFF_P3 + 128 * EX_P_LD * 4)     // 77824

__global__ __launch_bounds__(256, 1) void k_edgex(const float* __restrict__ SP) {
    extern __shared__ char S[];
    int t = threadIdx.x;
    int w = t >> 5;
    int tile = blockIdx.x;

    __nv_bfloat16* sSPh = (__nv_bfloat16*)(S + EXOFF_SPH);
    __nv_bfloat16* sSPl = (__nv_bfloat16*)(S + EXOFF_SPL);
    __nv_bfloat16* sWh  = (__nv_bfloat16*)(S + EXOFF_WH);
    __nv_bfloat16* sWl  = (__nv_bfloat16*)(S + EXOFF_WL);
    float* P2 = (float*)(S + EXOFF_P2);
    float* P3 = (float*)(S + EXOFF_P3);

    // load SP tile [128,32] split hi/lo; weights hi/lo
    for (int i = t; i < 1024; i += 256) {         // 128 rows x 8 float4
        int r = i >> 3, c4 = (i & 7) << 2;
        pack4(sSPh, sSPl, r * EX_SP_LD + c4, *(const float4*)&SP[(size_t)(tile * 128 + r) * KE + c4]);
    }
    for (int i = t; i < 512; i += 256) {          // 128 rows x 4 uint4(8 bf16)
        int r = i >> 2, sg = (i & 3) << 3;
        *(uint4*)&sWh[r * EX_W_LD + sg] = *(const uint4*)&g_W25h[r * KE + sg];
        *(uint4*)&sWl[r * EX_W_LD + sg] = *(const uint4*)&g_W25l[r * KE + sg];
    }
    __syncthreads();

    // warp w -> rows [w*16, w*16+16), full 128 output cols
    wmma::fragment<wmma::matrix_a, 16, 16, 16, __nv_bfloat16, wmma::row_major> ah[2], al[2];
#pragma unroll
    for (int kf = 0; kf < 2; kf++) {
        wmma::load_matrix_sync(ah[kf], sSPh + w * 16 * EX_SP_LD + kf * 16, EX_SP_LD);
        wmma::load_matrix_sync(al[kf], sSPl + w * 16 * EX_SP_LD + kf * 16, EX_SP_LD);
    }
#pragma unroll
    for (int nf = 0; nf < 8; nf++) {
        wmma::fragment<wmma::accumulator, 16, 16, 16, float> acc;
        wmma::fill_fragment(acc, 0.f);
#pragma unroll
        for (int kf = 0; kf < 2; kf++) {
            wmma::fragment<wmma::matrix_b, 16, 16, 16, __nv_bfloat16, wmma::col_major> bh, bl;
            wmma::load_matrix_sync(bh, sWh + nf * 16 * EX_W_LD + kf * 16, EX_W_LD);
            wmma::load_matrix_sync(bl, sWl + nf * 16 * EX_W_LD + kf * 16, EX_W_LD);
            wmma::mma_sync(acc, ah[kf], bh, acc);
            wmma::mma_sync(acc, ah[kf], bl, acc);
            wmma::mma_sync(acc, al[kf], bh, acc);
        }
        if (nf < 2) {
            wmma::store_matrix_sync(P2 + w * 16 * EX_P_LD + nf * 16, acc, EX_P_LD, wmma::mem_row_major);
        } else if (nf < 4) {
            wmma::store_matrix_sync(P3 + w * 16 * EX_P_LD + (nf - 2) * 16, acc, EX_P_LD, wmma::mem_row_major);
        } else if (nf < 6) {
            wmma::store_matrix_sync(g_X4 + (size_t)(tile * 128 + w * 16) * KE + (nf - 4) * 16,
                                    acc, KE, wmma::mem_row_major);
        } else {
            wmma::store_matrix_sync(g_X5 + (size_t)(tile * 128 + w * 16) * KE + (nf - 6) * 16,
                                    acc, KE, wmma::mem_row_major);
        }
    }
    __syncthreads();
    // g_prod = X2p * X3p (elementwise)
    for (int i = t; i < 4096; i += 256) {
        int r = i >> 5, c = i & 31;
        g_prod[(size_t)(tile * 128 + r) * KE + c] = P2[r * EX_P_LD + c] * P3[r * EX_P_LD + c];
    }
}

__global__ void k_build(const int* __restrict__ ei) {
    int e = blockIdx.x * blockDim.x + threadIdx.x;
    if (e < N_EDGES) {
        int s = ei[e], d = ei[N_EDGES + e];
        g_eid[s * N_NODES + d] = e;
        atomicAdd(&g_rowcnt[s], 1);
    }
}

__global__ void k_scan() {
    __shared__ int s[N_NODES];
    int t = threadIdx.x;
    s[t] = g_rowcnt[t];
    __syncthreads();
    for (int off = 1; off < N_NODES; off <<= 1) {
        int v = (t >= off) ? s[t - off] : 0;
        __syncthreads();
        s[t] += v;
        __syncthreads();
    }
    g_rowptr[t + 1] = s[t];
    if (t == 0) g_rowptr[0] = 0;
}

__global__ void k_fill(const int* __restrict__ ei) {
    int e = blockIdx.x * blockDim.x + threadIdx.x;
    if (e < N_EDGES) {
        int s = ei[e];
        int pos = atomicAdd(&g_fill[s], 1);
        g_rowedges[g_rowptr[s] + pos] = e;
    }
}

// sampled sparse-sparse matmul -> g_path
__global__ void k_path(const int* __restrict__ ei) {
    int warp = (blockIdx.x * blockDim.x + threadIdx.x) >> 5;
    int lane = threadIdx.x & 31;
    if (warp >= N_EDGES) return;
    int e = warp;
    int i = ei[e], j = ei[N_EDGES + e];
    int start = g_rowptr[i], end = g_rowptr[i + 1];
    float acc = 0.f;
    for (int s = start; s < end; s += 32) {
        int idx = s + lane;
        int e1 = -1, e2 = -1;
        if (idx < end) {
            e1 = g_rowedges[idx];
            int m = ei[N_EDGES + e1];
            e2 = g_eid[m * N_NODES + j];
        }
        unsigned mask = __ballot_sync(0xFFFFFFFFu, e2 >= 0);
        while (mask) {
            int b = __ffs(mask) - 1;
            mask &= mask - 1;
            int E1 = __shfl_sync(0xFFFFFFFFu, e1, b);
            int E2 = __shfl_sync(0xFFFFFFFFu, e2, b);
            acc += g_X4[E1 * KE + lane] * g_X5[E2 * KE + lane];
        }
    }
    g_path[(size_t)e * KE + lane] = acc;
}

// ---------------- fused WMMA edge MLP: EA = relu(TMP@W6^T)@W7^T ----------------
#define AS_LD   168
#define W6S_LD  168
#define W7S_LD  264
#define HS_LD   72
#define OFF_AH  0
#define OFF_AL  (OFF_AH + 128 * AS_LD * 2)        // 43008
#define OFF_W6H (OFF_AL + 128 * AS_LD * 2)        // 86016
#define OFF_W6L (OFF_W6H + 64 * W6S_LD * 2)       // 107520
#define OFF_W7H (OFF_W6L + 64 * W6S_LD * 2)       // 129024
#define OFF_W7L (OFF_W7H + 32 * W7S_LD * 2)       // 145920
#define OFF_HH  (OFF_W7L + 32 * W7S_LD * 2)       // 162816
#define OFF_HL  (OFF_HH + 128 * HS_LD * 2)        // 181248
#define SMEM_FUSED (OFF_HL + 128 * HS_LD * 2)     // 199680
#define OFF_CBUF OFF_W6H                          // fp32 128x68 reuses W6 region
#define CB_LD   68
#define EB_LD   36

__global__ __launch_bounds__(256, 1) void k_fused(const float* __restrict__ SP,
                                                  const int* __restrict__ ei,
                                                  float* __restrict__ EA) {
    extern __shared__ char S[];
    int t = threadIdx.x;
    int w = t >> 5, lane = t & 31;
    int tile = blockIdx.x;

    __nv_bfloat16* sAh  = (__nv_bfloat16*)(S + OFF_AH);
    __nv_bfloat16* sAl  = (__nv_bfloat16*)(S + OFF_AL);
    __nv_bfloat16* sW6h = (__nv_bfloat16*)(S + OFF_W6H);
    __nv_bfloat16* sW6l = (__nv_bfloat16*)(S + OFF_W6L);
    __nv_bfloat16* sW7h = (__nv_bfloat16*)(S + OFF_W7H);
    __nv_bfloat16* sW7l = (__nv_bfloat16*)(S + OFF_W7L);
    __nv_bfloat16* sHh  = (__nv_bfloat16*)(S + OFF_HH);
    __nv_bfloat16* sHl  = (__nv_bfloat16*)(S + OFF_HL);
    float* Cbuf = (float*)(S + OFF_CBUF);

    // ---- assemble A tile in bf16 hi/lo: [SP | prod | diag | path] ----
    {
        for (int i = t; i < 1024; i += 256) {           // 128 rows x 8 float4
            int r = i >> 3, c4 = (i & 7) << 2;
            size_t g = (size_t)(tile * 128 + r) * KE + c4;
            pack4(sAh, sAl, r * AS_LD + c4, *(const float4*)&SP[g]);
            pack4(sAh, sAl, r * AS_LD + 32 + c4, *(const float4*)&g_prod[g]);
            pack4(sAh, sAl, r * AS_LD + 128 + c4, *(const float4*)&g_path[g]);
        }
        for (int i = t; i < 128 * 32; i += 256) {       // zero diag cols [64:128)
            int r = i >> 5, u = i & 31;
            ((uint32_t*)&sAh[r * AS_LD + 64])[u] = 0u;
            ((uint32_t*)&sAl[r * AS_LD + 64])[u] = 0u;
        }
        const uint4* wH = (const uint4*)g_W7h;
        const uint4* wL = (const uint4*)g_W7l;
        for (int i = t; i < 32 * 32; i += 256) {
            int r = i / 32, sgi = i % 32;
            *(uint4*)&sW7h[r * W7S_LD + sgi * 8] = wH[i];
            *(uint4*)&sW7l[r * W7S_LD + sgi * 8] = wL[i];
        }
    }
    __syncthreads();
    // diag rows: overwrite zeros with h[src] where src==dst (rare)
    if (t < 128) {
        int e = tile * 128 + t;
        int si = ei[e], dj = ei[N_EDGES + e];
        if (si == dj) {
            for (int c = 0; c < 64; c++) {
                __nv_bfloat16 h, l;
                bf16_split(g_h[si * DNODE + c], h, l);
                sAh[t * AS_LD + 64 + c] = h;
                sAl[t * AS_LD + 64 + c] = l;
            }
        }
    }

    wmma::fragment<wmma::accumulator, 16, 16, 16, float> ea[2];
    wmma::fill_fragment(ea[0], 0.f);
    wmma::fill_fragment(ea[1], 0.f);

    for (int nc = 0; nc < 4; nc++) {
        __syncthreads();   // A/W7/diag ready (nc=0); Cbuf consumed (nc>0)
        {
            const uint4* bH = (const uint4*)(g_W6h + (size_t)nc * 64 * KW);
            const uint4* bL = (const uint4*)(g_W6l + (size_t)nc * 64 * KW);
            for (int i = t; i < 64 * 20; i += 256) {
                int r = i / 20, sgi = i % 20;
                *(uint4*)&sW6h[r * W6S_LD + sgi * 8] = bH[i];
                *(uint4*)&sW6l[r * W6S_LD + sgi * 8] = bL[i];
            }
        }
        __syncthreads();

        wmma::fragment<wmma::accumulator, 16, 16, 16, float> c[4];
#pragma unroll
        for (int n = 0; n < 4; n++) wmma::fill_fragment(c[n], 0.f);
#pragma unroll
        for (int k = 0; k < 10; k++) {
            wmma::fragment<wmma::matrix_a, 16, 16, 16, __nv_bfloat16, wmma::row_major> ah, al;
            wmma::load_matrix_sync(ah, sAh + w * 16 * AS_LD + k * 16, AS_LD);
            wmma::load_matrix_sync(al, sAl + w * 16 * AS_LD + k * 16, AS_LD);
#pragma unroll
            for (int n = 0; n < 4; n++) {
                wmma::fragment<wmma::matrix_b, 16, 16, 16, __nv_bfloat16, wmma::col_major> bh, bl;
                wmma::load_matrix_sync(bh, sW6h + n * 16 * W6S_LD + k * 16, W6S_LD);
                wmma::load_matrix_sync(bl, sW6l + n * 16 * W6S_LD + k * 16, W6S_LD);
                wmma::mma_sync(c[n], ah, bh, c[n]);
                wmma::mma_sync(c[n], ah, bl, c[n]);
                wmma::mma_sync(c[n], al, bh, c[n]);
            }
        }
        __syncthreads();   // all warps done reading W6 chunk; Cbuf region free

#pragma unroll
        for (int n = 0; n < 4; n++)
            wmma::store_matrix_sync(Cbuf + w * 16 * CB_LD + n * 16, c[n], CB_LD, wmma::mem_row_major);
        __syncwarp();
#pragma unroll
        for (int idx = 0; idx < 32; idx++) {
            int f = lane + idx * 32;
            int r = f >> 6, cc = f & 63;
            float v = fmaxf(Cbuf[(w * 16 + r) * CB_LD + cc], 0.f);
            __nv_bfloat16 h, l;
            bf16_split(v, h, l);
            sHh[(w * 16 + r) * HS_LD + cc] = h;
            sHl[(w * 16 + r) * HS_LD + cc] = l;
        }
        __syncwarp();

#pragma unroll
        for (int k2 = 0; k2 < 4; k2++) {
            wmma::fragment<wmma::matrix_a, 16, 16, 16, __nv_bfloat16, wmma::row_major> ah, al;
            wmma::load_matrix_sync(ah, sHh + w * 16 * HS_LD + k2 * 16, HS_LD);
            wmma::load_matrix_sync(al, sHl + w * 16 * HS_LD + k2 * 16, HS_LD);
#pragma unroll
            for (int n = 0; n < 2; n++) {
                wmma::fragment<wmma::matrix_b, 16, 16, 16, __nv_bfloat16, wmma::col_major> bh, bl;
                wmma::load_matrix_sync(bh, sW7h + n * 16 * W7S_LD + nc * 64 + k2 * 16, W7S_LD);
                wmma::load_matrix_sync(bl, sW7l + n * 16 * W7S_LD + nc * 64 + k2 * 16, W7S_LD);
                wmma::mma_sync(ea[n], ah, bh, ea[n]);
                wmma::mma_sync(ea[n], ah, bl, ea[n]);
                wmma::mma_sync(ea[n], al, bh, ea[n]);
            }
        }
    }

    __syncthreads();
    float* Ebuf = Cbuf;                        // 128 x 36 fp32
    wmma::store_matrix_sync(Ebuf + w * 16 * EB_LD, ea[0], EB_LD, wmma::mem_row_major);
    wmma::store_matrix_sync(Ebuf + w * 16 * EB_LD + 16, ea[1], EB_LD, wmma::mem_row_major);
    __syncthreads();
    for (int f = t; f < 1024; f += 256) {
        int r = f >> 3, sgi = f & 7;
        float4 v = *(float4*)&Ebuf[r * EB_LD + sgi * 4];
        *(float4*)&EA[((size_t)tile * 128 + r) * KOUT + sgi * 4] = v;
    }
}

// ---------------- aggregation (batched) + output ----------------
__global__ void k_agg(const float* __restrict__ x, const int* __restrict__ ei,
                      const float* __restrict__ EA) {
    int i = blockIdx.x;
    int t = threadIdx.x;  // 256
    __shared__ float ea_b[8][33];
    __shared__ float x_b[8][64];
    __shared__ int elist[8], dlist[8];
    float acc[8];
#pragma unroll
    for (int q = 0; q < 8; q++) acc[q] = 0.f;
    int start = g_rowptr[i], end = g_rowptr[i + 1];
    int c = t & 63, k0 = t >> 6;
    for (int p = start; p < end; p += 8) {
        int nb = min(8, end - p);
        if (t < nb) {
            int e = g_rowedges[p + t];
            elist[t] = e;
            dlist[t] = ei[N_EDGES + e];
        }
        __syncthreads();
        for (int i2 = t; i2 < nb * 96; i2 += 256) {
            int b = i2 / 96, f = i2 % 96;
            if (f < 32) ea_b[b][f] = EA[(size_t)elist[b] * KOUT + f];
            else x_b[b][f - 32] = x[dlist[b] * DIN + f - 32];
        }
        __syncthreads();
        for (int b = 0; b < nb; b++) {
            float xv = x_b[b][c];
#pragma unroll
            for (int q = 0; q < 8; q++) acc[q] += ea_b[b][k0 + q * 4] * xv;
        }
        __syncthreads();
    }
#pragma unroll
    for (int q = 0; q < 8; q++) g_AGG[i * (KOUT * DIN) + t + q * 256] = acc[q];
}

__global__ void k_out(const float* __restrict__ CW, const float* __restrict__ CB,
                      float* __restrict__ xout) {
    __shared__ float As[32][32];
    __shared__ float Bs[32][68];
    int t = threadIdx.x;            // 256
    int tx = t & 15, ty = t >> 4;
    int rowBase = blockIdx.x * 32;
    const int KTOT = KOUT * DIN;    // 2048
    float acc[2][4] = {};
    for (int k0 = 0; k0 < KTOT; k0 += 32) {
        {
            int r = t >> 3, kk = (t & 7) << 2;
            float4 v = *(const float4*)&g_AGG[(rowBase + r) * KTOT + k0 + kk];
            *(float4*)&As[r][kk] = v;
        }
#pragma unroll
        for (int l = 0; l < 2; l++) {
            int fid = t + l * 256;
            int kk = fid >> 4, n4 = (fid & 15) << 2;
            float4 v = *(const float4*)&CW[(k0 + kk) * DOUT + n4];
            *(float4*)&Bs[kk][n4] = v;
        }
        __syncthreads();
#pragma unroll
        for (int kk = 0; kk < 32; kk++) {
            float a[2], b[4];
            a[0] = As[ty * 2][kk]; a[1] = As[ty * 2 + 1][kk];
            float4 bv = *(const float4*)&Bs[kk][tx * 4];
            b[0] = bv.x; b[1] = bv.y; b[2] = bv.z; b[3] = bv.w;
#pragma unroll
            for (int i = 0; i < 2; i++)
#pragma unroll
                for (int j = 0; j < 4; j++) acc[i][j] += a[i] * b[j];
        }
        __syncthreads();
    }
#pragma unroll
    for (int i = 0; i < 2; i++) {
        int r = rowBase + ty * 2 + i;
#pragma unroll
        for (int j = 0; j < 4; j++)
            xout[r * DOUT + tx * 4 + j] = acc[i][j] + CB[tx * 4 + j];
    }
}

// ---------------------------------------------------------------
extern "C" void kernel_launch(void* const* d_in, const int* in_sizes, int n_in,
                              void* d_out, int out_size) {
    const float* x     = (const float*)d_in[0];
    const int*   ei    = (const int*)  d_in[1];
    const float* SP    = (const float*)d_in[2];
    const float* Wnode = (const float*)d_in[4];
    const float* W2    = (const float*)d_in[5];
    const float* W3    = (const float*)d_in[6];
    const float* W4    = (const float*)d_in[7];
    const float* W5    = (const float*)d_in[8];
    const float* W6    = (const float*)d_in[9];
    const float* W7    = (const float*)d_in[10];
    const float* CW    = (const float*)d_in[11];
    const float* CB    = (const float*)d_in[12];

    float* xout = (float*)d_out;                       // [1024, 64]
    float* EA   = (float*)d_out + N_NODES * DOUT;      // [32768, 32]

    cudaFuncSetAttribute(k_fused, cudaFuncAttributeMaxDynamicSharedMemorySize, SMEM_FUSED);
    cudaFuncSetAttribute(k_edgex, cudaFuncAttributeMaxDynamicSharedMemorySize, SMEM_EDGEX);

    k_init<<<2048, 512>>>();
    k_h<<<N_NODES, 64>>>(x, Wnode);
    k_wconv<<<(HID * KW + KOUT * HID + 128 * KE + 255) / 256, 256>>>(W6, W7, W2, W3, W4, W5);
    k_edgex<<<N_TILES, 256, SMEM_EDGEX>>>(SP);
    k_build<<<N_EDGES / 256, 256>>>(ei);
    k_scan<<<1, 1024>>>();
    k_fill<<<N_EDGES / 256, 256>>>(ei);
    k_path<<<N_EDGES / 8, 256>>>(ei);
    k_fused<<<N_TILES, 256, SMEM_FUSED>>>(SP, ei, EA);
    k_agg<<<N_NODES, 256>>>(x, ei, EA);
    k_out<<<N_NODES / 32, 256>>>(CW, CB, xout);
}

// round 8
// speedup vs baseline: 1.1722x; 1.0374x over previous
#include <cuda_runtime.h>
#include <cuda_bf16.h>
#include <mma.h>
#include <cstdint>

using namespace nvcuda;

#define N_NODES 1024
#define N_EDGES 32768
#define KE 32
#define KOUT 32
#define DIN 64
#define DOUT 64
#define DNODE 64
#define KW 160
#define HID 256
#define N_TILES (N_EDGES / 128)   // 256

// -------- device scratch (static; no runtime allocation) --------
__device__ float g_h[N_NODES * DNODE];
__device__ float g_X4[N_EDGES * KE];
__device__ float g_X5[N_EDGES * KE];
__device__ float g_prod[N_EDGES * KE];    // (SP W2^T)*(SP W3^T)
__device__ float g_path[N_EDGES * KE];    // tmp_matmul
__device__ int   g_eid[N_NODES * N_NODES];
__device__ int   g_rowcnt[N_NODES];
__device__ int   g_fill[N_NODES];
__device__ int   g_rowptr[N_NODES + 1];
__device__ int   g_rowedges[N_EDGES];     // packed: (dst << 15) | e
__device__ float g_AGG[N_NODES * KOUT * DIN];

// bf16 two-term weights (row-major)
__device__ __align__(16) __nv_bfloat16 g_W6h[HID * KW];
__device__ __align__(16) __nv_bfloat16 g_W6l[HID * KW];
__device__ __align__(16) __nv_bfloat16 g_W7h[KOUT * HID];
__device__ __align__(16) __nv_bfloat16 g_W7l[KOUT * HID];
// concat(W2,W3,W4,W5) as [128 n][32 k] bf16 hi/lo
__device__ __align__(16) __nv_bfloat16 g_W25h[128 * KE];
__device__ __align__(16) __nv_bfloat16 g_W25l[128 * KE];

__device__ __forceinline__ void bf16_split(float v, __nv_bfloat16& h, __nv_bfloat16& l) {
    h = __float2bfloat16(v);
    l = __float2bfloat16(v - __bfloat162float(h));
}

__device__ __forceinline__ void pack4(__nv_bfloat16* H, __nv_bfloat16* L, int idx, float4 v) {
    __nv_bfloat16 h0, h1, h2, h3, l0, l1, l2, l3;
    bf16_split(v.x, h0, l0); bf16_split(v.y, h1, l1);
    bf16_split(v.z, h2, l2); bf16_split(v.w, h3, l3);
    __nv_bfloat162* ph = (__nv_bfloat162*)&H[idx];
    __nv_bfloat162* pl = (__nv_bfloat162*)&L[idx];
    __nv_bfloat162 a; a.x = h0; a.y = h1; ph[0] = a;
    __nv_bfloat162 b; b.x = h2; b.y = h3; ph[1] = b;
    __nv_bfloat162 c; c.x = l0; c.y = l1; pl[0] = c;
    __nv_bfloat162 d; d.x = l2; d.y = l3; pl[1] = d;
}

// ---------------- k_prep: eid clear + h GEMV + weight conversion, one kernel ----------------
#define NB_INIT 2048
#define NB_H    128
#define NB_W    104    // 104*512 = 53248 = 40960(W6) + 8192(W7) + 4096(W25)
#define NB_PREP (NB_INIT + NB_H + NB_W)

__global__ __launch_bounds__(512) void k_prep(const float* __restrict__ x,
                                              const float* __restrict__ Wnode,
                                              const float* __restrict__ W6,
                                              const float* __restrict__ W7,
                                              const float* __restrict__ W2,
                                              const float* __restrict__ W3,
                                              const float* __restrict__ W4,
                                              const float* __restrict__ W5) {
    int b = blockIdx.x;
    int t = threadIdx.x;
    if (b < NB_INIT) {
        int base = b * 512 + t;
        g_eid[base * 1] = -1;                    // 1M elems: grid-stride with exact fit
        // 2048*512 = 1,048,576 = N_NODES*N_NODES exactly -> one write each
        if (base < N_NODES) { g_rowcnt[base] = 0; g_fill[base] = 0; }
    } else if (b < NB_INIT + NB_H) {
        // 8 nodes per block: h = x @ Wnode^T
        __shared__ float ws[DNODE][DIN + 1];
        __shared__ float xs[8][DIN];
        for (int i = t; i < DNODE * DIN; i += 512) ws[i >> 6][i & 63] = Wnode[i];
        int nb = (b - NB_INIT) * 8;
        int sub = t >> 6, c = t & 63;
        xs[sub][c] = x[(nb + sub) * DIN + c];
        __syncthreads();
        float acc = 0.f;
#pragma unroll
        for (int j = 0; j < DIN; j++) acc += xs[sub][j] * ws[c][j];
        g_h[(nb + sub) * DNODE + c] = acc;
    } else {
        int i = (b - NB_INIT - NB_H) * 512 + t;
        if (i < HID * KW) {
            __nv_bfloat16 h, l;
            bf16_split(W6[i], h, l);
            g_W6h[i] = h; g_W6l[i] = l;
        } else if (i < HID * KW + KOUT * HID) {
            int j = i - HID * KW;
            __nv_bfloat16 h, l;
            bf16_split(W7[j], h, l);
            g_W7h[j] = h; g_W7l[j] = l;
        } else if (i < HID * KW + KOUT * HID + 128 * KE) {
            int j = i - (HID * KW + KOUT * HID);
            int m = j >> 10, r = j & 1023;
            const float* Ws = (m == 0) ? W2 : (m == 1) ? W3 : (m == 2) ? W4 : W5;
            __nv_bfloat16 h, l;
            bf16_split(Ws[r], h, l);
            g_W25h[j] = h; g_W25l[j] = l;
        }
    }
}

// ---- WMMA batched small GEMM + edge-table build ----
#define EX_SP_LD 40
#define EX_W_LD  40
#define EX_P_LD  36
#define EXOFF_SPH 0
#define EXOFF_SPL (EXOFF_SPH + 128 * EX_SP_LD * 2)
#define EXOFF_WH  (EXOFF_SPL + 128 * EX_SP_LD * 2)
#define EXOFF_WL  (EXOFF_WH + 128 * EX_W_LD * 2)
#define EXOFF_P2  (EXOFF_WL + 128 * EX_W_LD * 2)
#define EXOFF_P3  (EXOFF_P2 + 128 * EX_P_LD * 4)
#define SMEM_EDGEX (EXOFF_P3 + 128 * EX_P_LD * 4)     // 77824

__global__ __launch_bounds__(256, 1) void k_edgex(const float* __restrict__ SP,
                                                  const int* __restrict__ ei) {
    extern __shared__ char S[];
    int t = threadIdx.x;
    int w = t >> 5;
    int tile = blockIdx.x;

    // fold in k_build: this tile's 128 edges populate eid table + row counts
    if (t < 128) {
        int e = tile * 128 + t;
        int s = ei[e], d = ei[N_EDGES + e];
        g_eid[s * N_NODES + d] = e;
        atomicAdd(&g_rowcnt[s], 1);
    }

    __nv_bfloat16* sSPh = (__nv_bfloat16*)(S + EXOFF_SPH);
    __nv_bfloat16* sSPl = (__nv_bfloat16*)(S + EXOFF_SPL);
    __nv_bfloat16* sWh  = (__nv_bfloat16*)(S + EXOFF_WH);
    __nv_bfloat16* sWl  = (__nv_bfloat16*)(S + EXOFF_WL);
    float* P2 = (float*)(S + EXOFF_P2);
    float* P3 = (float*)(S + EXOFF_P3);

    for (int i = t; i < 1024; i += 256) {
        int r = i >> 3, c4 = (i & 7) << 2;
        pack4(sSPh, sSPl, r * EX_SP_LD + c4, *(const float4*)&SP[(size_t)(tile * 128 + r) * KE + c4]);
    }
    for (int i = t; i < 512; i += 256) {
        int r = i >> 2, sg = (i & 3) << 3;
        *(uint4*)&sWh[r * EX_W_LD + sg] = *(const uint4*)&g_W25h[r * KE + sg];
        *(uint4*)&sWl[r * EX_W_LD + sg] = *(const uint4*)&g_W25l[r * KE + sg];
    }
    __syncthreads();

    wmma::fragment<wmma::matrix_a, 16, 16, 16, __nv_bfloat16, wmma::row_major> ah[2], al[2];
#pragma unroll
    for (int kf = 0; kf < 2; kf++) {
        wmma::load_matrix_sync(ah[kf], sSPh + w * 16 * EX_SP_LD + kf * 16, EX_SP_LD);
        wmma::load_matrix_sync(al[kf], sSPl + w * 16 * EX_SP_LD + kf * 16, EX_SP_LD);
    }
#pragma unroll
    for (int nf = 0; nf < 8; nf++) {
        wmma::fragment<wmma::accumulator, 16, 16, 16, float> acc;
        wmma::fill_fragment(acc, 0.f);
#pragma unroll
        for (int kf = 0; kf < 2; kf++) {
            wmma::fragment<wmma::matrix_b, 16, 16, 16, __nv_bfloat16, wmma::col_major> bh, bl;
            wmma::load_matrix_sync(bh, sWh + nf * 16 * EX_W_LD + kf * 16, EX_W_LD);
            wmma::load_matrix_sync(bl, sWl + nf * 16 * EX_W_LD + kf * 16, EX_W_LD);
            wmma::mma_sync(acc, ah[kf], bh, acc);
            wmma::mma_sync(acc, ah[kf], bl, acc);
            wmma::mma_sync(acc, al[kf], bh, acc);
        }
        if (nf < 2) {
            wmma::store_matrix_sync(P2 + w * 16 * EX_P_LD + nf * 16, acc, EX_P_LD, wmma::mem_row_major);
        } else if (nf < 4) {
            wmma::store_matrix_sync(P3 + w * 16 * EX_P_LD + (nf - 2) * 16, acc, EX_P_LD, wmma::mem_row_major);
        } else if (nf < 6) {
            wmma::store_matrix_sync(g_X4 + (size_t)(tile * 128 + w * 16) * KE + (nf - 4) * 16,
                                    acc, KE, wmma::mem_row_major);
        } else {
            wmma::store_matrix_sync(g_X5 + (size_t)(tile * 128 + w * 16) * KE + (nf - 6) * 16,
                                    acc, KE, wmma::mem_row_major);
        }
    }
    __syncthreads();
    for (int i = t; i < 4096; i += 256) {
        int r = i >> 5, c = i & 31;
        g_prod[(size_t)(tile * 128 + r) * KE + c] = P2[r * EX_P_LD + c] * P3[r * EX_P_LD + c];
    }
}

__global__ void k_scan() {
    __shared__ int s[N_NODES];
    int t = threadIdx.x;
    s[t] = g_rowcnt[t];
    __syncthreads();
    for (int off = 1; off < N_NODES; off <<= 1) {
        int v = (t >= off) ? s[t - off] : 0;
        __syncthreads();
        s[t] += v;
        __syncthreads();
    }
    g_rowptr[t + 1] = s[t];
    if (t == 0) g_rowptr[0] = 0;
}

// scatter edges into CSR slots, packed with dst: (dst<<15)|e
__global__ void k_fill(const int* __restrict__ ei) {
    int e = blockIdx.x * blockDim.x + threadIdx.x;
    if (e < N_EDGES) {
        int s = ei[e], d = ei[N_EDGES + e];
        int pos = atomicAdd(&g_fill[s], 1);
        g_rowedges[g_rowptr[s] + pos] = e | (d << 15);
    }
}

// sampled sparse-sparse matmul -> g_path (2-deep dependent chain)
__global__ void k_path(const int* __restrict__ ei) {
    int warp = (blockIdx.x * blockDim.x + threadIdx.x) >> 5;
    int lane = threadIdx.x & 31;
    if (warp >= N_EDGES) return;
    int e = warp;
    int i = ei[e], j = ei[N_EDGES + e];
    int start = g_rowptr[i], end = g_rowptr[i + 1];
    float acc = 0.f;
    for (int s = start; s < end; s += 32) {
        int idx = s + lane;
        int e1 = -1, e2 = -1;
        if (idx < end) {
            int p = g_rowedges[idx];
            e1 = p & 0x7FFF;
            e2 = g_eid[(p >> 15) * N_NODES + j];
        }
        unsigned mask = __ballot_sync(0xFFFFFFFFu, e2 >= 0);
        while (mask) {
            int b = __ffs(mask) - 1;
            mask &= mask - 1;
            int E1 = __shfl_sync(0xFFFFFFFFu, e1, b);
            int E2 = __shfl_sync(0xFFFFFFFFu, e2, b);
            acc += g_X4[E1 * KE + lane] * g_X5[E2 * KE + lane];
        }
    }
    g_path[(size_t)e * KE + lane] = acc;
}

// ---------------- fused WMMA edge MLP ----------------
#define AS_LD   168
#define W6S_LD  168
#define W7S_LD  264
#define HS_LD   72
#define OFF_AH  0
#define OFF_AL  (OFF_AH + 128 * AS_LD * 2)
#define OFF_W6H (OFF_AL + 128 * AS_LD * 2)
#define OFF_W6L (OFF_W6H + 64 * W6S_LD * 2)
#define OFF_W7H (OFF_W6L + 64 * W6S_LD * 2)
#define OFF_W7L (OFF_W7H + 32 * W7S_LD * 2)
#define OFF_HH  (OFF_W7L + 32 * W7S_LD * 2)
#define OFF_HL  (OFF_HH + 128 * HS_LD * 2)
#define SMEM_FUSED (OFF_HL + 128 * HS_LD * 2)     // 199680
#define OFF_CBUF OFF_W6H
#define CB_LD   68
#define EB_LD   36

__global__ __launch_bounds__(256, 1) void k_fused(const float* __restrict__ SP,
                                                  const int* __restrict__ ei,
                                                  float* __restrict__ EA) {
    extern __shared__ char S[];
    int t = threadIdx.x;
    int w = t >> 5, lane = t & 31;
    int tile = blockIdx.x;

    __nv_bfloat16* sAh  = (__nv_bfloat16*)(S + OFF_AH);
    __nv_bfloat16* sAl  = (__nv_bfloat16*)(S + OFF_AL);
    __nv_bfloat16* sW6h = (__nv_bfloat16*)(S + OFF_W6H);
    __nv_bfloat16* sW6l = (__nv_bfloat16*)(S + OFF_W6L);
    __nv_bfloat16* sW7h = (__nv_bfloat16*)(S + OFF_W7H);
    __nv_bfloat16* sW7l = (__nv_bfloat16*)(S + OFF_W7L);
    __nv_bfloat16* sHh  = (__nv_bfloat16*)(S + OFF_HH);
    __nv_bfloat16* sHl  = (__nv_bfloat16*)(S + OFF_HL);
    float* Cbuf = (float*)(S + OFF_CBUF);

    {
        for (int i = t; i < 1024; i += 256) {
            int r = i >> 3, c4 = (i & 7) << 2;
            size_t g = (size_t)(tile * 128 + r) * KE + c4;
            pack4(sAh, sAl, r * AS_LD + c4, *(const float4*)&SP[g]);
            pack4(sAh, sAl, r * AS_LD + 32 + c4, *(const float4*)&g_prod[g]);
            pack4(sAh, sAl, r * AS_LD + 128 + c4, *(const float4*)&g_path[g]);
        }
        for (int i = t; i < 128 * 32; i += 256) {
            int r = i >> 5, u = i & 31;
            ((uint32_t*)&sAh[r * AS_LD + 64])[u] = 0u;
            ((uint32_t*)&sAl[r * AS_LD + 64])[u] = 0u;
        }
        const uint4* wH = (const uint4*)g_W7h;
        const uint4* wL = (const uint4*)g_W7l;
        for (int i = t; i < 32 * 32; i += 256) {
            int r = i / 32, sgi = i % 32;
            *(uint4*)&sW7h[r * W7S_LD + sgi * 8] = wH[i];
            *(uint4*)&sW7l[r * W7S_LD + sgi * 8] = wL[i];
        }
    }
    __syncthreads();
    if (t < 128) {
        int e = tile * 128 + t;
        int si = ei[e], dj = ei[N_EDGES + e];
        if (si == dj) {
            for (int c = 0; c < 64; c++) {
                __nv_bfloat16 h, l;
                bf16_split(g_h[si * DNODE + c], h, l);
                sAh[t * AS_LD + 64 + c] = h;
                sAl[t * AS_LD + 64 + c] = l;
            }
        }
    }

    wmma::fragment<wmma::accumulator, 16, 16, 16, float> ea[2];
    wmma::fill_fragment(ea[0], 0.f);
    wmma::fill_fragment(ea[1], 0.f);

    for (int nc = 0; nc < 4; nc++) {
        __syncthreads();
        {
            const uint4* bH = (const uint4*)(g_W6h + (size_t)nc * 64 * KW);
            const uint4* bL = (const uint4*)(g_W6l + (size_t)nc * 64 * KW);
            for (int i = t; i < 64 * 20; i += 256) {
                int r = i / 20, sgi = i % 20;
                *(uint4*)&sW6h[r * W6S_LD + sgi * 8] = bH[i];
                *(uint4*)&sW6l[r * W6S_LD + sgi * 8] = bL[i];
            }
        }
        __syncthreads();

        wmma::fragment<wmma::accumulator, 16, 16, 16, float> c[4];
#pragma unroll
        for (int n = 0; n < 4; n++) wmma::fill_fragment(c[n], 0.f);
#pragma unroll
        for (int k = 0; k < 10; k++) {
            wmma::fragment<wmma::matrix_a, 16, 16, 16, __nv_bfloat16, wmma::row_major> ah, al;
            wmma::load_matrix_sync(ah, sAh + w * 16 * AS_LD + k * 16, AS_LD);
            wmma::load_matrix_sync(al, sAl + w * 16 * AS_LD + k * 16, AS_LD);
#pragma unroll
            for (int n = 0; n < 4; n++) {
                wmma::fragment<wmma::matrix_b, 16, 16, 16, __nv_bfloat16, wmma::col_major> bh, bl;
                wmma::load_matrix_sync(bh, sW6h + n * 16 * W6S_LD + k * 16, W6S_LD);
                wmma::load_matrix_sync(bl, sW6l + n * 16 * W6S_LD + k * 16, W6S_LD);
                wmma::mma_sync(c[n], ah, bh, c[n]);
                wmma::mma_sync(c[n], ah, bl, c[n]);
                wmma::mma_sync(c[n], al, bh, c[n]);
            }
        }
        __syncthreads();

#pragma unroll
        for (int n = 0; n < 4; n++)
            wmma::store_matrix_sync(Cbuf + w * 16 * CB_LD + n * 16, c[n], CB_LD, wmma::mem_row_major);
        __syncwarp();
#pragma unroll
        for (int idx = 0; idx < 32; idx++) {
            int f = lane + idx * 32;
            int r = f >> 6, cc = f & 63;
            float v = fmaxf(Cbuf[(w * 16 + r) * CB_LD + cc], 0.f);
            __nv_bfloat16 h, l;
            bf16_split(v, h, l);
            sHh[(w * 16 + r) * HS_LD + cc] = h;
            sHl[(w * 16 + r) * HS_LD + cc] = l;
        }
        __syncwarp();

#pragma unroll
        for (int k2 = 0; k2 < 4; k2++) {
            wmma::fragment<wmma::matrix_a, 16, 16, 16, __nv_bfloat16, wmma::row_major> ah, al;
            wmma::load_matrix_sync(ah, sHh + w * 16 * HS_LD + k2 * 16, HS_LD);
            wmma::load_matrix_sync(al, sHl + w * 16 * HS_LD + k2 * 16, HS_LD);
#pragma unroll
            for (int n = 0; n < 2; n++) {
                wmma::fragment<wmma::matrix_b, 16, 16, 16, __nv_bfloat16, wmma::col_major> bh, bl;
                wmma::load_matrix_sync(bh, sW7h + n * 16 * W7S_LD + nc * 64 + k2 * 16, W7S_LD);
                wmma::load_matrix_sync(bl, sW7l + n * 16 * W7S_LD + nc * 64 + k2 * 16, W7S_LD);
                wmma::mma_sync(ea[n], ah, bh, ea[n]);
                wmma::mma_sync(ea[n], ah, bl, ea[n]);
                wmma::mma_sync(ea[n], al, bh, ea[n]);
            }
        }
    }

    __syncthreads();
    float* Ebuf = Cbuf;
    wmma::store_matrix_sync(Ebuf + w * 16 * EB_LD, ea[0], EB_LD, wmma::mem_row_major);
    wmma::store_matrix_sync(Ebuf + w * 16 * EB_LD + 16, ea[1], EB_LD, wmma::mem_row_major);
    __syncthreads();
    for (int f = t; f < 1024; f += 256) {
        int r = f >> 3, sgi = f & 7;
        float4 v = *(float4*)&Ebuf[r * EB_LD + sgi * 4];
        *(float4*)&EA[((size_t)tile * 128 + r) * KOUT + sgi * 4] = v;
    }
}

// ---------------- aggregation (batched) + output ----------------
__global__ void k_agg(const float* __restrict__ x, const int* __restrict__ ei,
                      const float* __restrict__ EA) {
    int i = blockIdx.x;
    int t = threadIdx.x;  // 256
    __shared__ float ea_b[8][33];
    __shared__ float x_b[8][64];
    __shared__ int elist[8], dlist[8];
    float acc[8];
#pragma unroll
    for (int q = 0; q < 8; q++) acc[q] = 0.f;
    int start = g_rowptr[i], end = g_rowptr[i + 1];
    int c = t & 63, k0 = t >> 6;
    for (int p = start; p < end; p += 8) {
        int nb = min(8, end - p);
        if (t < nb) {
            int pk = g_rowedges[p + t];
            elist[t] = pk & 0x7FFF;
            dlist[t] = pk >> 15;
        }
        __syncthreads();
        for (int i2 = t; i2 < nb * 96; i2 += 256) {
            int b = i2 / 96, f = i2 % 96;
            if (f < 32) ea_b[b][f] = EA[(size_t)elist[b] * KOUT + f];
            else x_b[b][f - 32] = x[dlist[b] * DIN + f - 32];
        }
        __syncthreads();
        for (int b = 0; b < nb; b++) {
            float xv = x_b[b][c];
#pragma unroll
            for (int q = 0; q < 8; q++) acc[q] += ea_b[b][k0 + q * 4] * xv;
        }
        __syncthreads();
    }
#pragma unroll
    for (int q = 0; q < 8; q++) g_AGG[i * (KOUT * DIN) + t + q * 256] = acc[q];
}

__global__ void k_out(const float* __restrict__ CW, const float* __restrict__ CB,
                      float* __restrict__ xout) {
    __shared__ float As[32][32];
    __shared__ float Bs[32][68];
    int t = threadIdx.x;
    int tx = t & 15, ty = t >> 4;
    int rowBase = blockIdx.x * 32;
    const int KTOT = KOUT * DIN;
    float acc[2][4] = {};
    for (int k0 = 0; k0 < KTOT; k0 += 32) {
        {
            int r = t >> 3, kk = (t & 7) << 2;
            float4 v = *(const float4*)&g_AGG[(rowBase + r) * KTOT + k0 + kk];
            *(float4*)&As[r][kk] = v;
        }
#pragma unroll
        for (int l = 0; l < 2; l++) {
            int fid = t + l * 256;
            int kk = fid >> 4, n4 = (fid & 15) << 2;
            float4 v = *(const float4*)&CW[(k0 + kk) * DOUT + n4];
            *(float4*)&Bs[kk][n4] = v;
        }
        __syncthreads();
#pragma unroll
        for (int kk = 0; kk < 32; kk++) {
            float a[2], b[4];
            a[0] = As[ty * 2][kk]; a[1] = As[ty * 2 + 1][kk];
            float4 bv = *(const float4*)&Bs[kk][tx * 4];
            b[0] = bv.x; b[1] = bv.y; b[2] = bv.z; b[3] = bv.w;
#pragma unroll
            for (int i = 0; i < 2; i++)
#pragma unroll
                for (int j = 0; j < 4; j++) acc[i][j] += a[i] * b[j];
        }
        __syncthreads();
    }
#pragma unroll
    for (int i = 0; i < 2; i++) {
        int r = rowBase + ty * 2 + i;
#pragma unroll
        for (int j = 0; j < 4; j++)
            xout[r * DOUT + tx * 4 + j] = acc[i][j] + CB[tx * 4 + j];
    }
}

// ---------------------------------------------------------------
extern "C" void kernel_launch(void* const* d_in, const int* in_sizes, int n_in,
                              void* d_out, int out_size) {
    const float* x     = (const float*)d_in[0];
    const int*   ei    = (const int*)  d_in[1];
    const float* SP    = (const float*)d_in[2];
    const float* Wnode = (const float*)d_in[4];
    const float* W2    = (const float*)d_in[5];
    const float* W3    = (const float*)d_in[6];
    const float* W4    = (const float*)d_in[7];
    const float* W5    = (const float*)d_in[8];
    const float* W6    = (const float*)d_in[9];
    const float* W7    = (const float*)d_in[10];
    const float* CW    = (const float*)d_in[11];
    const float* CB    = (const float*)d_in[12];

    float* xout = (float*)d_out;                       // [1024, 64]
    float* EA   = (float*)d_out + N_NODES * DOUT;      // [32768, 32]

    cudaFuncSetAttribute(k_fused, cudaFuncAttributeMaxDynamicSharedMemorySize, SMEM_FUSED);
    cudaFuncSetAttribute(k_edgex, cudaFuncAttributeMaxDynamicSharedMemorySize, SMEM_EDGEX);

    k_prep<<<NB_PREP, 512>>>(x, Wnode, W6, W7, W2, W3, W4, W5);   // 0
    k_edgex<<<N_TILES, 256, SMEM_EDGEX>>>(SP, ei);                // 1 (includes build)
    k_scan<<<1, 1024>>>();                                        // 2
    k_fill<<<N_EDGES / 256, 256>>>(ei);                           // 3
    k_path<<<N_EDGES / 8, 256>>>(ei);                             // 4
    k_fused<<<N_TILES, 256, SMEM_FUSED>>>(SP, ei, EA);            // 5
    k_agg<<<N_NODES, 256>>>(x, ei, EA);                           // 6
    k_out<<<N_NODES / 32, 256>>>(CW, CB, xout);                   // 7
}

// round 10
// speedup vs baseline: 1.2212x; 1.0418x over previous
#include <cuda_runtime.h>
#include <cuda_bf16.h>
#include <mma.h>
#include <cstdint>

using namespace nvcuda;

#define N_NODES 1024
#define N_EDGES 32768
#define KE 32
#define KOUT 32
#define DIN 64
#define DOUT 64
#define DNODE 64
#define KW 160
#define HID 256
#define N_TILES (N_EDGES / 128)   // 256
#define ROWCAP 128                // per-row edge bucket capacity

// -------- device scratch (static; no runtime allocation) --------
__device__ float g_h[N_NODES * DNODE];
__device__ float g_X4[N_EDGES * KE];
__device__ float g_X5[N_EDGES * KE];
__device__ float g_prod[N_EDGES * KE];    // (SP W2^T)*(SP W3^T)
__device__ float g_path[N_EDGES * KE];    // tmp_matmul
__device__ int   g_eid[N_NODES * N_NODES];    // BSS-zeroed; stores e+1, 0 = empty (never cleared)
__device__ int   g_rowcnt[N_NODES];
__device__ int   g_rowedges[N_NODES * ROWCAP];  // packed: (dst << 15) | e
__device__ float g_AGG[N_NODES * KOUT * DIN];

// bf16 two-term weights (row-major)
__device__ __align__(16) __nv_bfloat16 g_W6h[HID * KW];
__device__ __align__(16) __nv_bfloat16 g_W6l[HID * KW];
__device__ __align__(16) __nv_bfloat16 g_W7h[KOUT * HID];
__device__ __align__(16) __nv_bfloat16 g_W7l[KOUT * HID];
// concat(W2,W3,W4,W5) as [128 n][32 k] bf16 hi/lo
__device__ __align__(16) __nv_bfloat16 g_W25h[128 * KE];
__device__ __align__(16) __nv_bfloat16 g_W25l[128 * KE];

__device__ __forceinline__ void bf16_split(float v, __nv_bfloat16& h, __nv_bfloat16& l) {
    h = __float2bfloat16(v);
    l = __float2bfloat16(v - __bfloat162float(h));
}

__device__ __forceinline__ void pack4(__nv_bfloat16* H, __nv_bfloat16* L, int idx, float4 v) {
    __nv_bfloat16 h0, h1, h2, h3, l0, l1, l2, l3;
    bf16_split(v.x, h0, l0); bf16_split(v.y, h1, l1);
    bf16_split(v.z, h2, l2); bf16_split(v.w, h3, l3);
    __nv_bfloat162* ph = (__nv_bfloat162*)&H[idx];
    __nv_bfloat162* pl = (__nv_bfloat162*)&L[idx];
    __nv_bfloat162 a; a.x = h0; a.y = h1; ph[0] = a;
    __nv_bfloat162 b; b.x = h2; b.y = h3; ph[1] = b;
    __nv_bfloat162 c; c.x = l0; c.y = l1; pl[0] = c;
    __nv_bfloat162 d; d.x = l2; d.y = l3; pl[1] = d;
}

// ---------------- k_prep: rowcnt reset + h GEMV + weight conversion ----------------
#define NB_H    128
#define NB_W    104    // 104*512 = 53248 = 40960(W6) + 8192(W7) + 4096(W25)
#define NB_PREP (NB_H + NB_W + 2)

__global__ __launch_bounds__(512) void k_prep(const float* __restrict__ x,
                                              const float* __restrict__ Wnode,
                                              const float* __restrict__ W6,
                                              const float* __restrict__ W7,
                                              const float* __restrict__ W2,
                                              const float* __restrict__ W3,
                                              const float* __restrict__ W4,
                                              const float* __restrict__ W5) {
    int b = blockIdx.x;
    int t = threadIdx.x;
    if (b < NB_H) {
        // 8 nodes per block: h = x @ Wnode^T
        __shared__ float ws[DNODE][DIN + 1];
        __shared__ float xs[8][DIN];
        for (int i = t; i < DNODE * DIN; i += 512) ws[i >> 6][i & 63] = Wnode[i];
        int nb = b * 8;
        int sub = t >> 6, c = t & 63;
        xs[sub][c] = x[(nb + sub) * DIN + c];
        __syncthreads();
        float acc = 0.f;
#pragma unroll
        for (int j = 0; j < DIN; j++) acc += xs[sub][j] * ws[c][j];
        g_h[(nb + sub) * DNODE + c] = acc;
    } else if (b < NB_H + NB_W) {
        int i = (b - NB_H) * 512 + t;
        if (i < HID * KW) {
            __nv_bfloat16 h, l;
            bf16_split(W6[i], h, l);
            g_W6h[i] = h; g_W6l[i] = l;
        } else if (i < HID * KW + KOUT * HID) {
            int j = i - HID * KW;
            __nv_bfloat16 h, l;
            bf16_split(W7[j], h, l);
            g_W7h[j] = h; g_W7l[j] = l;
        } else if (i < HID * KW + KOUT * HID + 128 * KE) {
            int j = i - (HID * KW + KOUT * HID);
            int m = j >> 10, r = j & 1023;
            const float* Ws = (m == 0) ? W2 : (m == 1) ? W3 : (m == 2) ? W4 : W5;
            __nv_bfloat16 h, l;
            bf16_split(Ws[r], h, l);
            g_W25h[j] = h; g_W25l[j] = l;
        }
    } else {
        int i = (b - NB_H - NB_W) * 512 + t;
        if (i < N_NODES) g_rowcnt[i] = 0;
    }
}

// ---- WMMA batched small GEMM + edge-table build (eid sentinel e+1, bucket append) ----
#define EX_SP_LD 40
#define EX_W_LD  40
#define EX_P_LD  36
#define EXOFF_SPH 0
#define EXOFF_SPL (EXOFF_SPH + 128 * EX_SP_LD * 2)
#define EXOFF_WH  (EXOFF_SPL + 128 * EX_SP_LD * 2)
#define EXOFF_WL  (EXOFF_WH + 128 * EX_W_LD * 2)
#define EXOFF_P2  (EXOFF_WL + 128 * EX_W_LD * 2)
#define EXOFF_P3  (EXOFF_P2 + 128 * EX_P_LD * 4)
#define SMEM_EDGEX (EXOFF_P3 + 128 * EX_P_LD * 4)     // 77824

__global__ __launch_bounds__(256, 1) void k_edgex(const float* __restrict__ SP,
                                                  const int* __restrict__ ei) {
    extern __shared__ char S[];
    int t = threadIdx.x;
    int w = t >> 5;
    int tile = blockIdx.x;

    // build: this tile's 128 edges populate eid table (e+1) + row buckets
    if (t < 128) {
        int e = tile * 128 + t;
        int s = ei[e], d = ei[N_EDGES + e];
        g_eid[s * N_NODES + d] = e + 1;
        int pos = atomicAdd(&g_rowcnt[s], 1);
        g_rowedges[s * ROWCAP + pos] = e | (d << 15);
    }

    __nv_bfloat16* sSPh = (__nv_bfloat16*)(S + EXOFF_SPH);
    __nv_bfloat16* sSPl = (__nv_bfloat16*)(S + EXOFF_SPL);
    __nv_bfloat16* sWh  = (__nv_bfloat16*)(S + EXOFF_WH);
    __nv_bfloat16* sWl  = (__nv_bfloat16*)(S + EXOFF_WL);
    float* P2 = (float*)(S + EXOFF_P2);
    float* P3 = (float*)(S + EXOFF_P3);

    for (int i = t; i < 1024; i += 256) {
        int r = i >> 3, c4 = (i & 7) << 2;
        pack4(sSPh, sSPl, r * EX_SP_LD + c4, *(const float4*)&SP[(size_t)(tile * 128 + r) * KE + c4]);
    }
    for (int i = t; i < 512; i += 256) {
        int r = i >> 2, sg = (i & 3) << 3;
        *(uint4*)&sWh[r * EX_W_LD + sg] = *(const uint4*)&g_W25h[r * KE + sg];
        *(uint4*)&sWl[r * EX_W_LD + sg] = *(const uint4*)&g_W25l[r * KE + sg];
    }
    __syncthreads();

    wmma::fragment<wmma::matrix_a, 16, 16, 16, __nv_bfloat16, wmma::row_major> ah[2], al[2];
#pragma unroll
    for (int kf = 0; kf < 2; kf++) {
        wmma::load_matrix_sync(ah[kf], sSPh + w * 16 * EX_SP_LD + kf * 16, EX_SP_LD);
        wmma::load_matrix_sync(al[kf], sSPl + w * 16 * EX_SP_LD + kf * 16, EX_SP_LD);
    }
#pragma unroll
    for (int nf = 0; nf < 8; nf++) {
        wmma::fragment<wmma::accumulator, 16, 16, 16, float> acc;
        wmma::fill_fragment(acc, 0.f);
#pragma unroll
        for (int kf = 0; kf < 2; kf++) {
            wmma::fragment<wmma::matrix_b, 16, 16, 16, __nv_bfloat16, wmma::col_major> bh, bl;
            wmma::load_matrix_sync(bh, sWh + nf * 16 * EX_W_LD + kf * 16, EX_W_LD);
            wmma::load_matrix_sync(bl, sWl + nf * 16 * EX_W_LD + kf * 16, EX_W_LD);
            wmma::mma_sync(acc, ah[kf], bh, acc);
            wmma::mma_sync(acc, ah[kf], bl, acc);
            wmma::mma_sync(acc, al[kf], bh, acc);
        }
        if (nf < 2) {
            wmma::store_matrix_sync(P2 + w * 16 * EX_P_LD + nf * 16, acc, EX_P_LD, wmma::mem_row_major);
        } else if (nf < 4) {
            wmma::store_matrix_sync(P3 + w * 16 * EX_P_LD + (nf - 2) * 16, acc, EX_P_LD, wmma::mem_row_major);
        } else if (nf < 6) {
            wmma::store_matrix_sync(g_X4 + (size_t)(tile * 128 + w * 16) * KE + (nf - 4) * 16,
                                    acc, KE, wmma::mem_row_major);
        } else {
            wmma::store_matrix_sync(g_X5 + (size_t)(tile * 128 + w * 16) * KE + (nf - 6) * 16,
                                    acc, KE, wmma::mem_row_major);
        }
    }
    __syncthreads();
    for (int i = t; i < 4096; i += 256) {
        int r = i >> 5, c = i & 31;
        g_prod[(size_t)(tile * 128 + r) * KE + c] = P2[r * EX_P_LD + c] * P3[r * EX_P_LD + c];
    }
}

// sampled sparse-sparse matmul -> g_path
__global__ void k_path(const int* __restrict__ ei) {
    int warp = (blockIdx.x * blockDim.x + threadIdx.x) >> 5;
    int lane = threadIdx.x & 31;
    if (warp >= N_EDGES) return;
    int e = warp;
    int i = ei[e], j = ei[N_EDGES + e];
    int start = i * ROWCAP;
    int end = start + g_rowcnt[i];
    float acc = 0.f;
    for (int s = start; s < end; s += 32) {
        int idx = s + lane;
        int e1 = -1, e2 = -1;
        if (idx < end) {
            int p = g_rowedges[idx];
            e1 = p & 0x7FFF;
            e2 = g_eid[(p >> 15) * N_NODES + j] - 1;   // 0 sentinel -> -1
        }
        unsigned mask = __ballot_sync(0xFFFFFFFFu, e2 >= 0);
        while (mask) {
            int b = __ffs(mask) - 1;
            mask &= mask - 1;
            int E1 = __shfl_sync(0xFFFFFFFFu, e1, b);
            int E2 = __shfl_sync(0xFFFFFFFFu, e2, b);
            acc += g_X4[E1 * KE + lane] * g_X5[E2 * KE + lane];
        }
    }
    g_path[(size_t)e * KE + lane] = acc;
}

// ---------------- fused WMMA edge MLP ----------------
#define AS_LD   168
#define W6S_LD  168
#define W7S_LD  264
#define HS_LD   72
#define OFF_AH  0
#define OFF_AL  (OFF_AH + 128 * AS_LD * 2)
#define OFF_W6H (OFF_AL + 128 * AS_LD * 2)
#define OFF_W6L (OFF_W6H + 64 * W6S_LD * 2)
#define OFF_W7H (OFF_W6L + 64 * W6S_LD * 2)
#define OFF_W7L (OFF_W7H + 32 * W7S_LD * 2)
#define OFF_HH  (OFF_W7L + 32 * W7S_LD * 2)
#define OFF_HL  (OFF_HH + 128 * HS_LD * 2)
#define SMEM_FUSED (OFF_HL + 128 * HS_LD * 2)     // 199680
#define OFF_CBUF OFF_W6H
#define CB_LD   68
#define EB_LD   36

__global__ __launch_bounds__(256, 1) void k_fused(const float* __restrict__ SP,
                                                  const int* __restrict__ ei,
                                                  float* __restrict__ EA) {
    extern __shared__ char S[];
    int t = threadIdx.x;
    int w = t >> 5, lane = t & 31;
    int tile = blockIdx.x;

    __nv_bfloat16* sAh  = (__nv_bfloat16*)(S + OFF_AH);
    __nv_bfloat16* sAl  = (__nv_bfloat16*)(S + OFF_AL);
    __nv_bfloat16* sW6h = (__nv_bfloat16*)(S + OFF_W6H);
    __nv_bfloat16* sW6l = (__nv_bfloat16*)(S + OFF_W6L);
    __nv_bfloat16* sW7h = (__nv_bfloat16*)(S + OFF_W7H);
    __nv_bfloat16* sW7l = (__nv_bfloat16*)(S + OFF_W7L);
    __nv_bfloat16* sHh  = (__nv_bfloat16*)(S + OFF_HH);
    __nv_bfloat16* sHl  = (__nv_bfloat16*)(S + OFF_HL);
    float* Cbuf = (float*)(S + OFF_CBUF);

    {
        for (int i = t; i < 1024; i += 256) {
            int r = i >> 3, c4 = (i & 7) << 2;
            size_t g = (size_t)(tile * 128 + r) * KE + c4;
            pack4(sAh, sAl, r * AS_LD + c4, *(const float4*)&SP[g]);
            pack4(sAh, sAl, r * AS_LD + 32 + c4, *(const float4*)&g_prod[g]);
            pack4(sAh, sAl, r * AS_LD + 128 + c4, *(const float4*)&g_path[g]);
        }
        for (int i = t; i < 128 * 32; i += 256) {
            int r = i >> 5, u = i & 31;
            ((uint32_t*)&sAh[r * AS_LD + 64])[u] = 0u;
            ((uint32_t*)&sAl[r * AS_LD + 64])[u] = 0u;
        }
        const uint4* wH = (const uint4*)g_W7h;
        const uint4* wL = (const uint4*)g_W7l;
        for (int i = t; i < 32 * 32; i += 256) {
            int r = i / 32, sgi = i % 32;
            *(uint4*)&sW7h[r * W7S_LD + sgi * 8] = wH[i];
            *(uint4*)&sW7l[r * W7S_LD + sgi * 8] = wL[i];
        }
    }
    __syncthreads();
    if (t < 128) {
        int e = tile * 128 + t;
        int si = ei[e], dj = ei[N_EDGES + e];
        if (si == dj) {
            for (int c = 0; c < 64; c++) {
                __nv_bfloat16 h, l;
                bf16_split(g_h[si * DNODE + c], h, l);
                sAh[t * AS_LD + 64 + c] = h;
                sAl[t * AS_LD + 64 + c] = l;
            }
        }
    }

    wmma::fragment<wmma::accumulator, 16, 16, 16, float> ea[2];
    wmma::fill_fragment(ea[0], 0.f);
    wmma::fill_fragment(ea[1], 0.f);

    for (int nc = 0; nc < 4; nc++) {
        __syncthreads();
        {
            const uint4* bH = (const uint4*)(g_W6h + (size_t)nc * 64 * KW);
            const uint4* bL = (const uint4*)(g_W6l + (size_t)nc * 64 * KW);
            for (int i = t; i < 64 * 20; i += 256) {
                int r = i / 20, sgi = i % 20;
                *(uint4*)&sW6h[r * W6S_LD + sgi * 8] = bH[i];
                *(uint4*)&sW6l[r * W6S_LD + sgi * 8] = bL[i];
            }
        }
        __syncthreads();

        wmma::fragment<wmma::accumulator, 16, 16, 16, float> c[4];
#pragma unroll
        for (int n = 0; n < 4; n++) wmma::fill_fragment(c[n], 0.f);
#pragma unroll
        for (int k = 0; k < 10; k++) {
            wmma::fragment<wmma::matrix_a, 16, 16, 16, __nv_bfloat16, wmma::row_major> ah, al;
            wmma::load_matrix_sync(ah, sAh + w * 16 * AS_LD + k * 16, AS_LD);
            wmma::load_matrix_sync(al, sAl + w * 16 * AS_LD + k * 16, AS_LD);
#pragma unroll
            for (int n = 0; n < 4; n++) {
                wmma::fragment<wmma::matrix_b, 16, 16, 16, __nv_bfloat16, wmma::col_major> bh, bl;
                wmma::load_matrix_sync(bh, sW6h + n * 16 * W6S_LD + k * 16, W6S_LD);
                wmma::load_matrix_sync(bl, sW6l + n * 16 * W6S_LD + k * 16, W6S_LD);
                wmma::mma_sync(c[n], ah, bh, c[n]);
                wmma::mma_sync(c[n], ah, bl, c[n]);
                wmma::mma_sync(c[n], al, bh, c[n]);
            }
        }
        __syncthreads();

#pragma unroll
        for (int n = 0; n < 4; n++)
            wmma::store_matrix_sync(Cbuf + w * 16 * CB_LD + n * 16, c[n], CB_LD, wmma::mem_row_major);
        __syncwarp();
#pragma unroll
        for (int idx = 0; idx < 32; idx++) {
            int f = lane + idx * 32;
            int r = f >> 6, cc = f & 63;
            float v = fmaxf(Cbuf[(w * 16 + r) * CB_LD + cc], 0.f);
            __nv_bfloat16 h, l;
            bf16_split(v, h, l);
            sHh[(w * 16 + r) * HS_LD + cc] = h;
            sHl[(w * 16 + r) * HS_LD + cc] = l;
        }
        __syncwarp();

#pragma unroll
        for (int k2 = 0; k2 < 4; k2++) {
            wmma::fragment<wmma::matrix_a, 16, 16, 16, __nv_bfloat16, wmma::row_major> ah, al;
            wmma::load_matrix_sync(ah, sHh + w * 16 * HS_LD + k2 * 16, HS_LD);
            wmma::load_matrix_sync(al, sHl + w * 16 * HS_LD + k2 * 16, HS_LD);
#pragma unroll
            for (int n = 0; n < 2; n++) {
                wmma::fragment<wmma::matrix_b, 16, 16, 16, __nv_bfloat16, wmma::col_major> bh, bl;
                wmma::load_matrix_sync(bh, sW7h + n * 16 * W7S_LD + nc * 64 + k2 * 16, W7S_LD);
                wmma::load_matrix_sync(bl, sW7l + n * 16 * W7S_LD + nc * 64 + k2 * 16, W7S_LD);
                wmma::mma_sync(ea[n], ah, bh, ea[n]);
                wmma::mma_sync(ea[n], ah, bl, ea[n]);
                wmma::mma_sync(ea[n], al, bh, ea[n]);
            }
        }
    }

    __syncthreads();
    float* Ebuf = Cbuf;
    wmma::store_matrix_sync(Ebuf + w * 16 * EB_LD, ea[0], EB_LD, wmma::mem_row_major);
    wmma::store_matrix_sync(Ebuf + w * 16 * EB_LD + 16, ea[1], EB_LD, wmma::mem_row_major);
    __syncthreads();
    for (int f = t; f < 1024; f += 256) {
        int r = f >> 3, sgi = f & 7;
        float4 v = *(float4*)&Ebuf[r * EB_LD + sgi * 4];
        *(float4*)&EA[((size_t)tile * 128 + r) * KOUT + sgi * 4] = v;
    }
}

// ---------------- aggregation (batched, bucket-based) + output ----------------
__global__ void k_agg(const float* __restrict__ x, const int* __restrict__ ei,
                      const float* __restrict__ EA) {
    int i = blockIdx.x;
    int t = threadIdx.x;  // 256
    __shared__ float ea_b[8][33];
    __shared__ float x_b[8][64];
    __shared__ int elist[8], dlist[8];
    float acc[8];
#pragma unroll
    for (int q = 0; q < 8; q++) acc[q] = 0.f;
    int start = i * ROWCAP;
    int end = start + g_rowcnt[i];
    int c = t & 63, k0 = t >> 6;
    for (int p = start; p < end; p += 8) {
        int nb = min(8, end - p);
        if (t < nb) {
            int pk = g_rowedges[p + t];
            elist[t] = pk & 0x7FFF;
            dlist[t] = pk >> 15;
        }
        __syncthreads();
        for (int i2 = t; i2 < nb * 96; i2 += 256) {
            int b = i2 / 96, f = i2 % 96;
            if (f < 32) ea_b[b][f] = EA[(size_t)elist[b] * KOUT + f];
            else x_b[b][f - 32] = x[dlist[b] * DIN + f - 32];
        }
        __syncthreads();
        for (int b = 0; b < nb; b++) {
            float xv = x_b[b][c];
#pragma unroll
            for (int q = 0; q < 8; q++) acc[q] += ea_b[b][k0 + q * 4] * xv;
        }
        __syncthreads();
    }
#pragma unroll
    for (int q = 0; q < 8; q++) g_AGG[i * (KOUT * DIN) + t + q * 256] = acc[q];
}

__global__ void k_out(const float* __restrict__ CW, const float* __restrict__ CB,
                      float* __restrict__ xout) {
    __shared__ float As[32][32];
    __shared__ float Bs[32][68];
    int t = threadIdx.x;
    int tx = t & 15, ty = t >> 4;
    int rowBase = blockIdx.x * 32;
    const int KTOT = KOUT * DIN;
    float acc[2][4] = {};
    for (int k0 = 0; k0 < KTOT; k0 += 32) {
        {
            int r = t >> 3, kk = (t & 7) << 2;
            float4 v = *(const float4*)&g_AGG[(rowBase + r) * KTOT + k0 + kk];
            *(float4*)&As[r][kk] = v;
        }
#pragma unroll
        for (int l = 0; l < 2; l++) {
            int fid = t + l * 256;
            int kk = fid >> 4, n4 = (fid & 15) << 2;
            float4 v = *(const float4*)&CW[(k0 + kk) * DOUT + n4];
            *(float4*)&Bs[kk][n4] = v;
        }
        __syncthreads();
#pragma unroll
        for (int kk = 0; kk < 32; kk++) {
            float a[2], b[4];
            a[0] = As[ty * 2][kk]; a[1] = As[ty * 2 + 1][kk];
            float4 bv = *(const float4*)&Bs[kk][tx * 4];
            b[0] = bv.x; b[1] = bv.y; b[2] = bv.z; b[3] = bv.w;
#pragma unroll
            for (int i = 0; i < 2; i++)
#pragma unroll
                for (int j = 0; j < 4; j++) acc[i][j] += a[i] * b[j];
        }
        __syncthreads();
    }
#pragma unroll
    for (int i = 0; i < 2; i++) {
        int r = rowBase + ty * 2 + i;
#pragma unroll
        for (int j = 0; j < 4; j++)
            xout[r * DOUT + tx * 4 + j] = acc[i][j] + CB[tx * 4 + j];
    }
}

// ---------------------------------------------------------------
extern "C" void kernel_launch(void* const* d_in, const int* in_sizes, int n_in,
                              void* d_out, int out_size) {
    const float* x     = (const float*)d_in[0];
    const int*   ei    = (const int*)  d_in[1];
    const float* SP    = (const float*)d_in[2];
    const float* Wnode = (const float*)d_in[4];
    const float* W2    = (const float*)d_in[5];
    const float* W3    = (const float*)d_in[6];
    const float* W4    = (const float*)d_in[7];
    const float* W5    = (const float*)d_in[8];
    const float* W6    = (const float*)d_in[9];
    const float* W7    = (const float*)d_in[10];
    const float* CW    = (const float*)d_in[11];
    const float* CB    = (const float*)d_in[12];

    float* xout = (float*)d_out;                       // [1024, 64]
    float* EA   = (float*)d_out + N_NODES * DOUT;      // [32768, 32]

    cudaFuncSetAttribute(k_fused, cudaFuncAttributeMaxDynamicSharedMemorySize, SMEM_FUSED);
    cudaFuncSetAttribute(k_edgex, cudaFuncAttributeMaxDynamicSharedMemorySize, SMEM_EDGEX);

    k_prep<<<NB_PREP, 512>>>(x, Wnode, W6, W7, W2, W3, W4, W5);   // 0
    k_edgex<<<N_TILES, 256, SMEM_EDGEX>>>(SP, ei);                // 1 (incl. build)
    k_path<<<N_EDGES / 8, 256>>>(ei);                             // 2
    k_fused<<<N_TILES, 256, SMEM_FUSED>>>(SP, ei, EA);            // 3
    k_agg<<<N_NODES, 256>>>(x, ei, EA);                           // 4
    k_out<<<N_NODES / 32, 256>>>(CW, CB, xout);                   // 5
}

// round 12
// speedup vs baseline: 1.2535x; 1.0265x over previous
#include <cuda_runtime.h>
#include <cuda_bf16.h>
#include <mma.h>
#include <cstdint>

using namespace nvcuda;

#define N_NODES 1024
#define N_EDGES 32768
#define KE 32
#define KOUT 32
#define DIN 64
#define DOUT 64
#define DNODE 64
#define KW 160
#define HID 256
#define N_TILES (N_EDGES / 128)   // 256 (edgex tiles)
#define ROWCAP 128

// -------- device scratch (static; no runtime allocation) --------
__device__ float g_h[N_NODES * DNODE];
__device__ float g_X4[N_EDGES * KE];
__device__ float g_X5[N_EDGES * KE];
__device__ float g_prod[N_EDGES * KE];
__device__ float g_path[N_EDGES * KE];
__device__ int   g_eid[N_NODES * N_NODES];    // BSS-zeroed; stores e+1, 0 = empty
__device__ int   g_rowcnt[N_NODES];
__device__ int   g_rowedges[N_NODES * ROWCAP];  // packed: (dst << 15) | e
__device__ float g_AGG[N_NODES * KOUT * DIN];

__device__ __align__(16) __nv_bfloat16 g_W6h[HID * KW];
__device__ __align__(16) __nv_bfloat16 g_W6l[HID * KW];
__device__ __align__(16) __nv_bfloat16 g_W7h[KOUT * HID];
__device__ __align__(16) __nv_bfloat16 g_W7l[KOUT * HID];
__device__ __align__(16) __nv_bfloat16 g_W25h[128 * KE];
__device__ __align__(16) __nv_bfloat16 g_W25l[128 * KE];

__device__ __forceinline__ void bf16_split(float v, __nv_bfloat16& h, __nv_bfloat16& l) {
    h = __float2bfloat16(v);
    l = __float2bfloat16(v - __bfloat162float(h));
}

__device__ __forceinline__ void pack4(__nv_bfloat16* H, __nv_bfloat16* L, int idx, float4 v) {
    __nv_bfloat16 h0, h1, h2, h3, l0, l1, l2, l3;
    bf16_split(v.x, h0, l0); bf16_split(v.y, h1, l1);
    bf16_split(v.z, h2, l2); bf16_split(v.w, h3, l3);
    __nv_bfloat162* ph = (__nv_bfloat162*)&H[idx];
    __nv_bfloat162* pl = (__nv_bfloat162*)&L[idx];
    __nv_bfloat162 a; a.x = h0; a.y = h1; ph[0] = a;
    __nv_bfloat162 b; b.x = h2; b.y = h3; ph[1] = b;
    __nv_bfloat162 c; c.x = l0; c.y = l1; pl[0] = c;
    __nv_bfloat162 d; d.x = l2; d.y = l3; pl[1] = d;
}

// ---------------- k_prep ----------------
#define NB_H    128
#define NB_W    104
#define NB_PREP (NB_H + NB_W + 2)

__global__ __launch_bounds__(512) void k_prep(const float* __restrict__ x,
                                              const float* __restrict__ Wnode,
                                              const float* __restrict__ W6,
                                              const float* __restrict__ W7,
                                              const float* __restrict__ W2,
                                              const float* __restrict__ W3,
                                              const float* __restrict__ W4,
                                              const float* __restrict__ W5) {
    int b = blockIdx.x;
    int t = threadIdx.x;
    if (b < NB_H) {
        __shared__ float ws[DNODE][DIN + 1];
        __shared__ float xs[8][DIN];
        for (int i = t; i < DNODE * DIN; i += 512) ws[i >> 6][i & 63] = Wnode[i];
        int nb = b * 8;
        int sub = t >> 6, c = t & 63;
        xs[sub][c] = x[(nb + sub) * DIN + c];
        __syncthreads();
        float acc = 0.f;
#pragma unroll
        for (int j = 0; j < DIN; j++) acc += xs[sub][j] * ws[c][j];
        g_h[(nb + sub) * DNODE + c] = acc;
    } else if (b < NB_H + NB_W) {
        int i = (b - NB_H) * 512 + t;
        if (i < HID * KW) {
            __nv_bfloat16 h, l;
            bf16_split(W6[i], h, l);
            g_W6h[i] = h; g_W6l[i] = l;
        } else if (i < HID * KW + KOUT * HID) {
            int j = i - HID * KW;
            __nv_bfloat16 h, l;
            bf16_split(W7[j], h, l);
            g_W7h[j] = h; g_W7l[j] = l;
        } else if (i < HID * KW + KOUT * HID + 128 * KE) {
            int j = i - (HID * KW + KOUT * HID);
            int m = j >> 10, r = j & 1023;
            const float* Ws = (m == 0) ? W2 : (m == 1) ? W3 : (m == 2) ? W4 : W5;
            __nv_bfloat16 h, l;
            bf16_split(Ws[r], h, l);
            g_W25h[j] = h; g_W25l[j] = l;
        }
    } else {
        int i = (b - NB_H - NB_W) * 512 + t;
        if (i < N_NODES) g_rowcnt[i] = 0;
    }
}

// ---- WMMA batched small GEMM + edge-table build ----
#define EX_SP_LD 40
#define EX_W_LD  40
#define EX_P_LD  36
#define EXOFF_SPH 0
#define EXOFF_SPL (EXOFF_SPH + 128 * EX_SP_LD * 2)
#define EXOFF_WH  (EXOFF_SPL + 128 * EX_SP_LD * 2)
#define EXOFF_WL  (EXOFF_WH + 128 * EX_W_LD * 2)
#define EXOFF_P2  (EXOFF_WL + 128 * EX_W_LD * 2)
#define EXOFF_P3  (EXOFF_P2 + 128 * EX_P_LD * 4)
#define SMEM_EDGEX (EXOFF_P3 + 128 * EX_P_LD * 4)     // 77824

__global__ __launch_bounds__(256, 1) void k_edgex(const float* __restrict__ SP,
                                                  const int* __restrict__ ei) {
    extern __shared__ char S[];
    int t = threadIdx.x;
    int w = t >> 5;
    int tile = blockIdx.x;

    if (t < 128) {
        int e = tile * 128 + t;
        int s = ei[e], d = ei[N_EDGES + e];
        g_eid[s * N_NODES + d] = e + 1;
        int pos = atomicAdd(&g_rowcnt[s], 1);
        g_rowedges[s * ROWCAP + pos] = e | (d << 15);
    }

    __nv_bfloat16* sSPh = (__nv_bfloat16*)(S + EXOFF_SPH);
    __nv_bfloat16* sSPl = (__nv_bfloat16*)(S + EXOFF_SPL);
    __nv_bfloat16* sWh  = (__nv_bfloat16*)(S + EXOFF_WH);
    __nv_bfloat16* sWl  = (__nv_bfloat16*)(S + EXOFF_WL);
    float* P2 = (float*)(S + EXOFF_P2);
    float* P3 = (float*)(S + EXOFF_P3);

    for (int i = t; i < 1024; i += 256) {
        int r = i >> 3, c4 = (i & 7) << 2;
        pack4(sSPh, sSPl, r * EX_SP_LD + c4, *(const float4*)&SP[(size_t)(tile * 128 + r) * KE + c4]);
    }
    for (int i = t; i < 512; i += 256) {
        int r = i >> 2, sg = (i & 3) << 3;
        *(uint4*)&sWh[r * EX_W_LD + sg] = *(const uint4*)&g_W25h[r * KE + sg];
        *(uint4*)&sWl[r * EX_W_LD + sg] = *(const uint4*)&g_W25l[r * KE + sg];
    }
    __syncthreads();

    wmma::fragment<wmma::matrix_a, 16, 16, 16, __nv_bfloat16, wmma::row_major> ah[2], al[2];
#pragma unroll
    for (int kf = 0; kf < 2; kf++) {
        wmma::load_matrix_sync(ah[kf], sSPh + w * 16 * EX_SP_LD + kf * 16, EX_SP_LD);
        wmma::load_matrix_sync(al[kf], sSPl + w * 16 * EX_SP_LD + kf * 16, EX_SP_LD);
    }
#pragma unroll
    for (int nf = 0; nf < 8; nf++) {
        wmma::fragment<wmma::accumulator, 16, 16, 16, float> acc;
        wmma::fill_fragment(acc, 0.f);
#pragma unroll
        for (int kf = 0; kf < 2; kf++) {
            wmma::fragment<wmma::matrix_b, 16, 16, 16, __nv_bfloat16, wmma::col_major> bh, bl;
            wmma::load_matrix_sync(bh, sWh + nf * 16 * EX_W_LD + kf * 16, EX_W_LD);
            wmma::load_matrix_sync(bl, sWl + nf * 16 * EX_W_LD + kf * 16, EX_W_LD);
            wmma::mma_sync(acc, ah[kf], bh, acc);
            wmma::mma_sync(acc, ah[kf], bl, acc);
            wmma::mma_sync(acc, al[kf], bh, acc);
        }
        if (nf < 2) {
            wmma::store_matrix_sync(P2 + w * 16 * EX_P_LD + nf * 16, acc, EX_P_LD, wmma::mem_row_major);
        } else if (nf < 4) {
            wmma::store_matrix_sync(P3 + w * 16 * EX_P_LD + (nf - 2) * 16, acc, EX_P_LD, wmma::mem_row_major);
        } else if (nf < 6) {
            wmma::store_matrix_sync(g_X4 + (size_t)(tile * 128 + w * 16) * KE + (nf - 4) * 16,
                                    acc, KE, wmma::mem_row_major);
        } else {
            wmma::store_matrix_sync(g_X5 + (size_t)(tile * 128 + w * 16) * KE + (nf - 6) * 16,
                                    acc, KE, wmma::mem_row_major);
        }
    }
    __syncthreads();
    for (int i = t; i < 4096; i += 256) {
        int r = i >> 5, c = i & 31;
        g_prod[(size_t)(tile * 128 + r) * KE + c] = P2[r * EX_P_LD + c] * P3[r * EX_P_LD + c];
    }
}

// sampled sparse-sparse matmul -> g_path
__global__ void k_path(const int* __restrict__ ei) {
    int warp = (blockIdx.x * blockDim.x + threadIdx.x) >> 5;
    int lane = threadIdx.x & 31;
    if (warp >= N_EDGES) return;
    int e = warp;
    int i = ei[e], j = ei[N_EDGES + e];
    int start = i * ROWCAP;
    int end = start + g_rowcnt[i];
    float acc = 0.f;
    for (int s = start; s < end; s += 32) {
        int idx = s + lane;
        int e1 = -1, e2 = -1;
        if (idx < end) {
            int p = g_rowedges[idx];
            e1 = p & 0x7FFF;
            e2 = g_eid[(p >> 15) * N_NODES + j] - 1;
        }
        unsigned mask = __ballot_sync(0xFFFFFFFFu, e2 >= 0);
        while (mask) {
            int b = __ffs(mask) - 1;
            mask &= mask - 1;
            int E1 = __shfl_sync(0xFFFFFFFFu, e1, b);
            int E2 = __shfl_sync(0xFFFFFFFFu, e2, b);
            acc += g_X4[E1 * KE + lane] * g_X5[E2 * KE + lane];
        }
    }
    g_path[(size_t)e * KE + lane] = acc;
}

// ---------------- fused WMMA edge MLP (64-row tiles, 2 CTAs/SM) ----------------
#define FM      64
#define FGRID   (N_EDGES / FM)     // 512
#define AS_LD   168
#define W6S_LD  168
#define W7S_LD  72
#define HS_LD   72
#define OFF_AH  0
#define OFF_AL  (OFF_AH + FM * AS_LD * 2)            // 21504
#define OFF_W6H (OFF_AL + FM * AS_LD * 2)            // 43008
#define OFF_W6L (OFF_W6H + 64 * W6S_LD * 2)          // 64512
#define OFF_W7H (OFF_W6L + 64 * W6S_LD * 2)          // 86016
#define OFF_W7L (OFF_W7H + 32 * W7S_LD * 2)          // 90624
#define OFF_HH  (OFF_W7L + 32 * W7S_LD * 2)          // 95232
#define OFF_HL  (OFF_HH + FM * HS_LD * 2)            // 104448
#define SMEM_FUSED (OFF_HL + FM * HS_LD * 2)         // 113664
#define OFF_CBUF OFF_W6H                              // fp32 64x68 = 17408 (< W6 region)
#define CB_LD   68
#define EB_LD   36

__global__ __launch_bounds__(256, 2) void k_fused(const float* __restrict__ SP,
                                                  const int* __restrict__ ei,
                                                  float* __restrict__ EA) {
    extern __shared__ char S[];
    int t = threadIdx.x;
    int w = t >> 5, lane = t & 31;
    int wm = w >> 1, wn = w & 1;       // 4 M-subtiles x 2 N-subtiles
    int tile = blockIdx.x;

    __nv_bfloat16* sAh  = (__nv_bfloat16*)(S + OFF_AH);
    __nv_bfloat16* sAl  = (__nv_bfloat16*)(S + OFF_AL);
    __nv_bfloat16* sW6h = (__nv_bfloat16*)(S + OFF_W6H);
    __nv_bfloat16* sW6l = (__nv_bfloat16*)(S + OFF_W6L);
    __nv_bfloat16* sW7h = (__nv_bfloat16*)(S + OFF_W7H);
    __nv_bfloat16* sW7l = (__nv_bfloat16*)(S + OFF_W7L);
    __nv_bfloat16* sHh  = (__nv_bfloat16*)(S + OFF_HH);
    __nv_bfloat16* sHl  = (__nv_bfloat16*)(S + OFF_HL);
    float* Cbuf = (float*)(S + OFF_CBUF);

    // ---- assemble A tile [64 x 160] bf16 hi/lo ----
    for (int i = t; i < FM * 8; i += 256) {           // 64 rows x 8 float4
        int r = i >> 3, c4 = (i & 7) << 2;
        size_t g = (size_t)(tile * FM + r) * KE + c4;
        pack4(sAh, sAl, r * AS_LD + c4, *(const float4*)&SP[g]);
        pack4(sAh, sAl, r * AS_LD + 32 + c4, *(const float4*)&g_prod[g]);
        pack4(sAh, sAl, r * AS_LD + 128 + c4, *(const float4*)&g_path[g]);
    }
    for (int i = t; i < FM * 32; i += 256) {          // zero diag cols [64:128)
        int r = i >> 5, u = i & 31;
        ((uint32_t*)&sAh[r * AS_LD + 64])[u] = 0u;
        ((uint32_t*)&sAl[r * AS_LD + 64])[u] = 0u;
    }
    __syncthreads();
    if (t < FM) {
        int e = tile * FM + t;
        int si = ei[e], dj = ei[N_EDGES + e];
        if (si == dj) {
            for (int c = 0; c < 64; c++) {
                __nv_bfloat16 h, l;
                bf16_split(g_h[si * DNODE + c], h, l);
                sAh[t * AS_LD + 64 + c] = h;
                sAl[t * AS_LD + 64 + c] = l;
            }
        }
    }

    wmma::fragment<wmma::accumulator, 16, 16, 16, float> ea;
    wmma::fill_fragment(ea, 0.f);

    for (int nc = 0; nc < 4; nc++) {
        __syncthreads();   // A/diag ready (nc=0); Cbuf consumed (nc>0)
        // load W6 chunk [64 x 160] and W7 chunk [32 x 64] (cols nc*64..)
        {
            const uint4* bH = (const uint4*)(g_W6h + (size_t)nc * 64 * KW);
            const uint4* bL = (const uint4*)(g_W6l + (size_t)nc * 64 * KW);
            for (int i = t; i < 64 * 20; i += 256) {
                int r = i / 20, sgi = i % 20;
                *(uint4*)&sW6h[r * W6S_LD + sgi * 8] = bH[i];
                *(uint4*)&sW6l[r * W6S_LD + sgi * 8] = bL[i];
            }
            // W7 chunk: 32 rows x 8 uint4 = 256 over 256 threads
            int r = t >> 3, sg = t & 7;
            *(uint4*)&sW7h[r * W7S_LD + sg * 8] = *(const uint4*)&g_W7h[r * HID + nc * 64 + sg * 8];
            *(uint4*)&sW7l[r * W7S_LD + sg * 8] = *(const uint4*)&g_W7l[r * HID + nc * 64 + sg * 8];
        }
        __syncthreads();

        // GEMM1 chunk: C[64,64] = A[64,160] @ W6c^T; warp (wm,wn) -> rows wm*16, cols wn*32
        wmma::fragment<wmma::accumulator, 16, 16, 16, float> c[2];
        wmma::fill_fragment(c[0], 0.f);
        wmma::fill_fragment(c[1], 0.f);
#pragma unroll
        for (int k = 0; k < 10; k++) {
            wmma::fragment<wmma::matrix_a, 16, 16, 16, __nv_bfloat16, wmma::row_major> ah, al;
            wmma::load_matrix_sync(ah, sAh + wm * 16 * AS_LD + k * 16, AS_LD);
            wmma::load_matrix_sync(al, sAl + wm * 16 * AS_LD + k * 16, AS_LD);
#pragma unroll
            for (int n = 0; n < 2; n++) {
                wmma::fragment<wmma::matrix_b, 16, 16, 16, __nv_bfloat16, wmma::col_major> bh, bl;
                wmma::load_matrix_sync(bh, sW6h + (wn * 32 + n * 16) * W6S_LD + k * 16, W6S_LD);
                wmma::load_matrix_sync(bl, sW6l + (wn * 32 + n * 16) * W6S_LD + k * 16, W6S_LD);
                wmma::mma_sync(c[n], ah, bh, c[n]);
                wmma::mma_sync(c[n], ah, bl, c[n]);
                wmma::mma_sync(c[n], al, bh, c[n]);
            }
        }
        __syncthreads();   // all warps done reading W6 chunk; Cbuf region free

        // store fp32 C (warp piece), relu + split -> H (warp-local)
        wmma::store_matrix_sync(Cbuf + wm * 16 * CB_LD + wn * 32, c[0], CB_LD, wmma::mem_row_major);
        wmma::store_matrix_sync(Cbuf + wm * 16 * CB_LD + wn * 32 + 16, c[1], CB_LD, wmma::mem_row_major);
        __syncwarp();
#pragma unroll
        for (int idx = 0; idx < 16; idx++) {
            int f = lane + idx * 32;           // 0..511 : 16 rows x 32 cols
            int r = f >> 5, cc = f & 31;
            float v = fmaxf(Cbuf[(wm * 16 + r) * CB_LD + wn * 32 + cc], 0.f);
            __nv_bfloat16 h, l;
            bf16_split(v, h, l);
            sHh[(wm * 16 + r) * HS_LD + wn * 32 + cc] = h;
            sHl[(wm * 16 + r) * HS_LD + wn * 32 + cc] = l;
        }
        __syncthreads();   // H chunk complete (GEMM2 A spans both wn halves)

        // GEMM2 partial: ea += Hc[16,64] @ W7c^T ; warp cols wn*16
#pragma unroll
        for (int k2 = 0; k2 < 4; k2++) {
            wmma::fragment<wmma::matrix_a, 16, 16, 16, __nv_bfloat16, wmma::row_major> ah, al;
            wmma::load_matrix_sync(ah, sHh + wm * 16 * HS_LD + k2 * 16, HS_LD);
            wmma::load_matrix_sync(al, sHl + wm * 16 * HS_LD + k2 * 16, HS_LD);
            wmma::fragment<wmma::matrix_b, 16, 16, 16, __nv_bfloat16, wmma::col_major> bh, bl;
            wmma::load_matrix_sync(bh, sW7h + wn * 16 * W7S_LD + k2 * 16, W7S_LD);
            wmma::load_matrix_sync(bl, sW7l + wn * 16 * W7S_LD + k2 * 16, W7S_LD);
            wmma::mma_sync(ea, ah, bh, ea);
            wmma::mma_sync(ea, ah, bl, ea);
            wmma::mma_sync(ea, al, bh, ea);
        }
    }

    // epilogue
    __syncthreads();
    float* Ebuf = Cbuf;                        // 64 x 36 fp32
    wmma::store_matrix_sync(Ebuf + wm * 16 * EB_LD + wn * 16, ea, EB_LD, wmma::mem_row_major);
    __syncthreads();
    for (int f = t; f < FM * 8; f += 256) {    // 64 rows x 8 float4
        int r = f >> 3, sgi = f & 7;
        float4 v = *(float4*)&Ebuf[r * EB_LD + sgi * 4];
        *(float4*)&EA[((size_t)tile * FM + r) * KOUT + sgi * 4] = v;
    }
}

// ---------------- aggregation + output ----------------
__global__ void k_agg(const float* __restrict__ x, const int* __restrict__ ei,
                      const float* __restrict__ EA) {
    int i = blockIdx.x;
    int t = threadIdx.x;  // 256
    __shared__ float ea_b[8][33];
    __shared__ float x_b[8][64];
    __shared__ int elist[8], dlist[8];
    float acc[8];
#pragma unroll
    for (int q = 0; q < 8; q++) acc[q] = 0.f;
    int start = i * ROWCAP;
    int end = start + g_rowcnt[i];
    int c = t & 63, k0 = t >> 6;
    for (int p = start; p < end; p += 8) {
        int nb = min(8, end - p);
        if (t < nb) {
            int pk = g_rowedges[p + t];
            elist[t] = pk & 0x7FFF;
            dlist[t] = pk >> 15;
        }
        __syncthreads();
        for (int i2 = t; i2 < nb * 96; i2 += 256) {
            int b = i2 / 96, f = i2 % 96;
            if (f < 32) ea_b[b][f] = EA[(size_t)elist[b] * KOUT + f];
            else x_b[b][f - 32] = x[dlist[b] * DIN + f - 32];
        }
        __syncthreads();
        for (int b = 0; b < nb; b++) {
            float xv = x_b[b][c];
#pragma unroll
            for (int q = 0; q < 8; q++) acc[q] += ea_b[b][k0 + q * 4] * xv;
        }
        __syncthreads();
    }
#pragma unroll
    for (int q = 0; q < 8; q++) g_AGG[i * (KOUT * DIN) + t + q * 256] = acc[q];
}

__global__ void k_out(const float* __restrict__ CW, const float* __restrict__ CB,
                      float* __restrict__ xout) {
    __shared__ float As[32][32];
    __shared__ float Bs[32][68];
    int t = threadIdx.x;
    int tx = t & 15, ty = t >> 4;
    int rowBase = blockIdx.x * 32;
    const int KTOT = KOUT * DIN;
    float acc[2][4] = {};
    for (int k0 = 0; k0 < KTOT; k0 += 32) {
        {
            int r = t >> 3, kk = (t & 7) << 2;
            float4 v = *(const float4*)&g_AGG[(rowBase + r) * KTOT + k0 + kk];
            *(float4*)&As[r][kk] = v;
        }
#pragma unroll
        for (int l = 0; l < 2; l++) {
            int fid = t + l * 256;
            int kk = fid >> 4, n4 = (fid & 15) << 2;
            float4 v = *(const float4*)&CW[(k0 + kk) * DOUT + n4];
            *(float4*)&Bs[kk][n4] = v;
        }
        __syncthreads();
#pragma unroll
        for (int kk = 0; kk < 32; kk++) {
            float a[2], b[4];
            a[0] = As[ty * 2][kk]; a[1] = As[ty * 2 + 1][kk];
            float4 bv = *(const float4*)&Bs[kk][tx * 4];
            b[0] = bv.x; b[1] = bv.y; b[2] = bv.z; b[3] = bv.w;
#pragma unroll
            for (int i = 0; i < 2; i++)
#pragma unroll
                for (int j = 0; j < 4; j++) acc[i][j] += a[i] * b[j];
        }
        __syncthreads();
    }
#pragma unroll
    for (int i = 0; i < 2; i++) {
        int r = rowBase + ty * 2 + i;
#pragma unroll
        for (int j = 0; j < 4; j++)
            xout[r * DOUT + tx * 4 + j] = acc[i][j] + CB[tx * 4 + j];
    }
}

// ---------------------------------------------------------------
extern "C" void kernel_launch(void* const* d_in, const int* in_sizes, int n_in,
                              void* d_out, int out_size) {
    const float* x     = (const float*)d_in[0];
    const int*   ei    = (const int*)  d_in[1];
    const float* SP    = (const float*)d_in[2];
    const float* Wnode = (const float*)d_in[4];
    const float* W2    = (const float*)d_in[5];
    const float* W3    = (const float*)d_in[6];
    const float* W4    = (const float*)d_in[7];
    const float* W5    = (const float*)d_in[8];
    const float* W6    = (const float*)d_in[9];
    const float* W7    = (const float*)d_in[10];
    const float* CW    = (const float*)d_in[11];
    const float* CB    = (const float*)d_in[12];

    float* xout = (float*)d_out;                       // [1024, 64]
    float* EA   = (float*)d_out + N_NODES * DOUT;      // [32768, 32]

    cudaFuncSetAttribute(k_fused, cudaFuncAttributeMaxDynamicSharedMemorySize, SMEM_FUSED);
    cudaFuncSetAttribute(k_edgex, cudaFuncAttributeMaxDynamicSharedMemorySize, SMEM_EDGEX);

    k_prep<<<NB_PREP, 512>>>(x, Wnode, W6, W7, W2, W3, W4, W5);   // 0
    k_edgex<<<N_TILES, 256, SMEM_EDGEX>>>(SP, ei);                // 1
    k_path<<<N_EDGES / 8, 256>>>(ei);                             // 2
    k_fused<<<FGRID, 256, SMEM_FUSED>>>(SP, ei, EA);              // 3
    k_agg<<<N_NODES, 256>>>(x, ei, EA);                           // 4
    k_out<<<N_NODES / 32, 256>>>(CW, CB, xout);                   // 5
}